// round 3
// baseline (speedup 1.0000x reference)
#include <cuda_runtime.h>
#include <cuda_fp16.h>
#include <math.h>
#include <stdint.h>

// Problem constants
constexpr int Bb  = 2;
constexpr int Ll  = 2048;
constexpr int Dd  = 512;
constexpr int Hh  = 8;
constexpr int HD  = 64;
constexpr int DH  = 2048;
constexpr int MREL = 128;
constexpr int D3  = 3 * Dd;    // 1536
constexpr int BL  = Bb * Ll;   // 4096
constexpr long long XSIZE  = (long long)BL * Dd;
constexpr long long ATTN_N = (long long)Bb * Hh * Ll * Ll;  // 67,108,864

// fp16 staging buffers
__device__ __half g_h16  [BL * Dd];
__device__ __half g_qkv16[BL * D3];
__device__ __half g_o16  [BL * Dd];
__device__ __half g_f16  [BL * DH];
__device__ __half g_attn16[ATTN_N];
// fp16 weights: qkv_w | out_w | ffn_in_w | ffn_out_w
constexpr long long OFF_QKVW   = 0;
constexpr long long OFF_OUTW   = OFF_QKVW  + (long long)Dd * D3;
constexpr long long OFF_FFNIN  = OFF_OUTW  + (long long)Dd * Dd;
constexpr long long OFF_FFNOUT = OFF_FFNIN + (long long)Dd * 2 * DH;
constexpr long long W16_TOTAL  = OFF_FFNOUT + (long long)DH * Dd;
__device__ __half g_w16[W16_TOTAL];
// fp32 scratch
__device__ float  g_x1  [BL * Dd];
__device__ float2 g_stats[Bb * Hh * Ll];   // per-row (max, sumexp)

// ---------------- helpers ----------------
static __device__ __forceinline__ uint32_t sm32(const void* p) {
    return (uint32_t)__cvta_generic_to_shared(p);
}
static __device__ __forceinline__ void ldsm_x4(uint32_t& r0, uint32_t& r1, uint32_t& r2, uint32_t& r3, uint32_t a) {
    asm volatile("ldmatrix.sync.aligned.m8n8.x4.shared.b16 {%0,%1,%2,%3}, [%4];\n"
                 : "=r"(r0), "=r"(r1), "=r"(r2), "=r"(r3) : "r"(a));
}
static __device__ __forceinline__ void ldsm_x2(uint32_t& r0, uint32_t& r1, uint32_t a) {
    asm volatile("ldmatrix.sync.aligned.m8n8.x2.shared.b16 {%0,%1}, [%2];\n"
                 : "=r"(r0), "=r"(r1) : "r"(a));
}
static __device__ __forceinline__ void ldsm_x2t(uint32_t& r0, uint32_t& r1, uint32_t a) {
    asm volatile("ldmatrix.sync.aligned.m8n8.x2.trans.shared.b16 {%0,%1}, [%2];\n"
                 : "=r"(r0), "=r"(r1) : "r"(a));
}
static __device__ __forceinline__ void mma16(float* c, const uint32_t* a, const uint32_t* b) {
    asm volatile("mma.sync.aligned.m16n8k16.row.col.f32.f16.f16.f32 "
                 "{%0,%1,%2,%3}, {%4,%5,%6,%7}, {%8,%9}, {%0,%1,%2,%3};\n"
                 : "+f"(c[0]), "+f"(c[1]), "+f"(c[2]), "+f"(c[3])
                 : "r"(a[0]), "r"(a[1]), "r"(a[2]), "r"(a[3]), "r"(b[0]), "r"(b[1]));
}
static __device__ __forceinline__ int clampq(int d) {
    return d < -(MREL - 1) ? -(MREL - 1) : (d > (MREL - 1) ? (MREL - 1) : d);
}

// ---------------- fp32 -> fp16 convert (vectorized) ----------------
__global__ void f2h_kernel(const float4* __restrict__ src, __half2* __restrict__ dst, long long n4) {
    long long i = (long long)blockIdx.x * blockDim.x + threadIdx.x;
    if (i < n4) {
        float4 v = src[i];
        dst[i * 2]     = __floats2half2_rn(v.x, v.y);
        dst[i * 2 + 1] = __floats2half2_rn(v.z, v.w);
    }
}

// ---------------- LayerNorm -> fp16 out ----------------
__global__ void ln_kernel(const float* __restrict__ x, const float* __restrict__ w,
                          const float* __restrict__ b, __half* __restrict__ out) {
    int row = blockIdx.x;
    const float* xr = x + (long long)row * Dd;
    int t = threadIdx.x; // 256
    float v0 = xr[t], v1 = xr[t + 256];
    __shared__ float red[256];
    red[t] = v0 + v1;
    __syncthreads();
    #pragma unroll
    for (int o = 128; o > 0; o >>= 1) { if (t < o) red[t] += red[t + o]; __syncthreads(); }
    float mu = red[0] * (1.0f / Dd);
    __syncthreads();
    float d0 = v0 - mu, d1 = v1 - mu;
    red[t] = d0 * d0 + d1 * d1;
    __syncthreads();
    #pragma unroll
    for (int o = 128; o > 0; o >>= 1) { if (t < o) red[t] += red[t + o]; __syncthreads(); }
    float rstd = rsqrtf(red[0] * (1.0f / Dd) + 1e-5f);
    __half* orow = out + (long long)row * Dd;
    orow[t]       = __float2half(d0 * rstd * w[t]       + b[t]);
    orow[t + 256] = __float2half(d1 * rstd * w[t + 256] + b[t + 256]);
}

// ---------------- Tensor-core GEMM with fused epilogues ----------------
// BM=128 BN=128 BK=32, 256 threads. MODE 0: half out = acc+bias.
// MODE 1: float out = resid + (acc+bias)*gamma.
template <int MODE>
__global__ void gemm16_kernel(const __half* __restrict__ A, const __half* __restrict__ W,
                              const float* __restrict__ bias, __half* __restrict__ Ch,
                              float* __restrict__ Cf, const float* __restrict__ resid,
                              const float* __restrict__ gamma, int N, int K) {
    __shared__ __half As[128][40];
    __shared__ __half Bs[32][136];
    int bm = blockIdx.y * 128, bn = blockIdx.x * 128;
    int tid = threadIdx.x, lane = tid & 31, wid = tid >> 5;
    int wm0 = (wid & 1) * 64, wn0 = (wid >> 1) * 32;
    float acc[4][4][4] = {};
    for (int k0 = 0; k0 < K; k0 += 32) {
        #pragma unroll
        for (int i = 0; i < 2; i++) {
            int t = tid + i * 256;
            int r = t >> 2, s = t & 3;
            *(uint4*)&As[r][s * 8] = *(const uint4*)(A + (size_t)(bm + r) * K + k0 + s * 8);
        }
        #pragma unroll
        for (int i = 0; i < 2; i++) {
            int t = tid + i * 256;
            int r = t >> 4, s = t & 15;
            *(uint4*)&Bs[r][s * 8] = *(const uint4*)(W + (size_t)(k0 + r) * N + bn + s * 8);
        }
        __syncthreads();
        #pragma unroll
        for (int ks = 0; ks < 32; ks += 16) {
            uint32_t a[4][4], b[4][2];
            #pragma unroll
            for (int i = 0; i < 4; i++)
                ldsm_x4(a[i][0], a[i][1], a[i][2], a[i][3],
                        sm32(&As[wm0 + i * 16 + (lane & 15)][ks + (lane >> 4) * 8]));
            #pragma unroll
            for (int j = 0; j < 4; j++)
                ldsm_x2t(b[j][0], b[j][1], sm32(&Bs[ks + (lane & 15)][wn0 + j * 8]));
            #pragma unroll
            for (int i = 0; i < 4; i++)
                #pragma unroll
                for (int j = 0; j < 4; j++) mma16(acc[i][j], a[i], b[j]);
        }
        __syncthreads();
    }
    #pragma unroll
    for (int i = 0; i < 4; i++) {
        #pragma unroll
        for (int j = 0; j < 4; j++) {
            int r = bm + wm0 + i * 16 + (lane >> 2);
            int c = bn + wn0 + j * 8 + (lane & 3) * 2;
            #pragma unroll
            for (int hh = 0; hh < 2; hh++) {
                size_t idx = (size_t)(r + hh * 8) * N + c;
                float v0 = acc[i][j][hh * 2]     + bias[c];
                float v1 = acc[i][j][hh * 2 + 1] + bias[c + 1];
                if (MODE == 0) {
                    Ch[idx]     = __float2half(v0);
                    Ch[idx + 1] = __float2half(v1);
                } else {
                    Cf[idx]     = resid[idx]     + v0 * gamma[c];
                    Cf[idx + 1] = resid[idx + 1] + v1 * gamma[c + 1];
                }
            }
        }
    }
}

// ---------------- S1: per-row softmax stats (max, sumexp); no score writes ----------------
// Block: 128 q-rows per (b,h); each of 8 warps owns 16 rows; k loops over 2048 in 128-tiles.
__global__ void stats_kernel(const __half* __restrict__ qkv, const float* __restrict__ rel_bias,
                             float2* __restrict__ stats) {
    int bh = blockIdx.y, b = bh >> 3, h = bh & 7;
    int q0 = blockIdx.x * 128;
    __shared__ __half Qs[128][72];
    __shared__ __half Ks[128][72];
    __shared__ float rb_s[2 * MREL - 1];
    int tid = threadIdx.x, lane = tid & 31, wid = tid >> 5;
    if (tid < 2 * MREL - 1) rb_s[tid] = rel_bias[h * (2 * MREL - 1) + tid];
    const __half* Qg = qkv + (size_t)b * Ll * D3 + h * HD;
    const __half* Kg = Qg + Dd;
    #pragma unroll
    for (int i = 0; i < 4; i++) {
        int t = tid + i * 256;
        int r = t >> 3, s = t & 7;
        *(uint4*)&Qs[r][s * 8] = *(const uint4*)(Qg + (size_t)(q0 + r) * D3 + s * 8);
    }
    const float scale = 0.125f;
    float m0 = -1e30f, m1 = -1e30f, l0 = 0.f, l1 = 0.f;
    int qrow0 = wid * 16 + (lane >> 2);      // local row (c0,c1)
    for (int k0 = 0; k0 < Ll; k0 += 128) {
        #pragma unroll
        for (int i = 0; i < 4; i++) {
            int t = tid + i * 256;
            int r = t >> 3, s = t & 7;
            *(uint4*)&Ks[r][s * 8] = *(const uint4*)(Kg + (size_t)(k0 + r) * D3 + s * 8);
        }
        __syncthreads();
        uint32_t a[4][4];
        #pragma unroll
        for (int kc = 0; kc < 4; kc++)
            ldsm_x4(a[kc][0], a[kc][1], a[kc][2], a[kc][3],
                    sm32(&Qs[wid * 16 + (lane & 15)][kc * 16 + (lane >> 4) * 8]));
        float acc[16][4];
        #pragma unroll
        for (int j = 0; j < 16; j++) {
            acc[j][0] = acc[j][1] = acc[j][2] = acc[j][3] = 0.f;
            #pragma unroll
            for (int kc = 0; kc < 4; kc++) {
                uint32_t bfr0, bfr1;
                ldsm_x2(bfr0, bfr1, sm32(&Ks[j * 8 + (lane & 7)][kc * 16 + ((lane >> 3) & 1) * 8]));
                uint32_t bfr[2] = {bfr0, bfr1};
                mma16(acc[j], a[kc], bfr);
            }
        }
        // transform to scores + tile max
        float tm0 = -1e30f, tm1 = -1e30f;
        int qg0 = q0 + qrow0, qg1 = qg0 + 8;
        #pragma unroll
        for (int j = 0; j < 16; j++) {
            int kk = k0 + j * 8 + (lane & 3) * 2;
            #pragma unroll
            for (int cc = 0; cc < 2; cc++) {
                float s0 = acc[j][cc]     * scale + rb_s[clampq(qg0 - (kk + cc)) + MREL - 1];
                float s1 = acc[j][cc + 2] * scale + rb_s[clampq(qg1 - (kk + cc)) + MREL - 1];
                acc[j][cc] = s0; acc[j][cc + 2] = s1;
                tm0 = fmaxf(tm0, s0); tm1 = fmaxf(tm1, s1);
            }
        }
        tm0 = fmaxf(tm0, __shfl_xor_sync(0xffffffffu, tm0, 1));
        tm0 = fmaxf(tm0, __shfl_xor_sync(0xffffffffu, tm0, 2));
        tm1 = fmaxf(tm1, __shfl_xor_sync(0xffffffffu, tm1, 1));
        tm1 = fmaxf(tm1, __shfl_xor_sync(0xffffffffu, tm1, 2));
        float mn0 = fmaxf(m0, tm0), mn1 = fmaxf(m1, tm1);
        float s0 = 0.f, s1 = 0.f;
        #pragma unroll
        for (int j = 0; j < 16; j++) {
            s0 += __expf(acc[j][0] - mn0) + __expf(acc[j][1] - mn0);
            s1 += __expf(acc[j][2] - mn1) + __expf(acc[j][3] - mn1);
        }
        l0 = l0 * __expf(m0 - mn0) + s0;
        l1 = l1 * __expf(m1 - mn1) + s1;
        m0 = mn0; m1 = mn1;
        __syncthreads();
    }
    l0 += __shfl_xor_sync(0xffffffffu, l0, 1);
    l0 += __shfl_xor_sync(0xffffffffu, l0, 2);
    l1 += __shfl_xor_sync(0xffffffffu, l1, 1);
    l1 += __shfl_xor_sync(0xffffffffu, l1, 2);
    if ((lane & 3) == 0) {
        stats[(size_t)bh * Ll + q0 + qrow0]     = make_float2(m0, l0);
        stats[(size_t)bh * Ll + q0 + qrow0 + 8] = make_float2(m1, l1);
    }
}

// ---------------- S2: recompute scores, emit softmax probs (fp32 + fp16) ----------------
__global__ void emit_kernel(const __half* __restrict__ qkv, const float* __restrict__ rel_bias,
                            const float2* __restrict__ stats, float* __restrict__ attn,
                            __half* __restrict__ attn16) {
    int bh = blockIdx.z, b = bh >> 3, h = bh & 7;
    int q0 = blockIdx.y * 128, k0 = blockIdx.x * 128;
    __shared__ __half Qs[128][72];
    __shared__ __half Ks[128][72];
    __shared__ float rb_s[2 * MREL - 1];
    __shared__ float2 st_s[128];
    int tid = threadIdx.x, lane = tid & 31, wid = tid >> 5;
    if (tid < 2 * MREL - 1) rb_s[tid] = rel_bias[h * (2 * MREL - 1) + tid];
    if (tid < 128) {
        float2 v = stats[(size_t)bh * Ll + q0 + tid];
        st_s[tid] = make_float2(v.x, 1.0f / v.y);
    }
    const __half* Qg = qkv + (size_t)b * Ll * D3 + h * HD;
    const __half* Kg = Qg + Dd;
    #pragma unroll
    for (int i = 0; i < 4; i++) {
        int t = tid + i * 256;
        int r = t >> 3, s = t & 7;
        *(uint4*)&Qs[r][s * 8] = *(const uint4*)(Qg + (size_t)(q0 + r) * D3 + s * 8);
        *(uint4*)&Ks[r][s * 8] = *(const uint4*)(Kg + (size_t)(k0 + r) * D3 + s * 8);
    }
    __syncthreads();
    int wm0 = (wid >> 1) * 32, wn0 = (wid & 1) * 64;
    float acc[2][8][4] = {};
    #pragma unroll
    for (int ks = 0; ks < 64; ks += 16) {
        uint32_t a[2][4], bfr[8][2];
        #pragma unroll
        for (int i = 0; i < 2; i++)
            ldsm_x4(a[i][0], a[i][1], a[i][2], a[i][3],
                    sm32(&Qs[wm0 + i * 16 + (lane & 15)][ks + (lane >> 4) * 8]));
        #pragma unroll
        for (int j = 0; j < 8; j++)
            ldsm_x2(bfr[j][0], bfr[j][1],
                    sm32(&Ks[wn0 + j * 8 + (lane & 7)][ks + ((lane >> 3) & 1) * 8]));
        #pragma unroll
        for (int i = 0; i < 2; i++)
            #pragma unroll
            for (int j = 0; j < 8; j++) mma16(acc[i][j], a[i], bfr[j]);
    }
    const float scale = 0.125f;
    #pragma unroll
    for (int i = 0; i < 2; i++) {
        #pragma unroll
        for (int j = 0; j < 8; j++) {
            #pragma unroll
            for (int half_ = 0; half_ < 2; half_++) {
                int ql = wm0 + i * 16 + (lane >> 2) + half_ * 8;
                int qq = q0 + ql;
                float2 st = st_s[ql];
                size_t row = ((size_t)bh * Ll + qq) * Ll;
                int kk = k0 + wn0 + j * 8 + (lane & 3) * 2;
                #pragma unroll
                for (int cc = 0; cc < 2; cc++) {
                    int kkk = kk + cc;
                    float s = acc[i][j][half_ * 2 + cc] * scale
                            + rb_s[clampq(qq - kkk) + MREL - 1];
                    float p = __expf(s - st.x) * st.y;
                    attn[row + kkk] = p;
                    attn16[row + kkk] = __float2half(p);
                }
            }
        }
    }
}

// ---------------- AV: o16[b,q,h,:] = attn16[b,h,q,:] @ V16[b,:,h,:] ----------------
__global__ void av16_kernel(const __half* __restrict__ attn16, const __half* __restrict__ qkv,
                            __half* __restrict__ o16) {
    int bh = blockIdx.z, b = bh >> 3, h = bh & 7;
    int q0 = blockIdx.x * 128;
    __shared__ __half As[128][72];
    __shared__ __half Vs[64][72];
    int tid = threadIdx.x, lane = tid & 31, wid = tid >> 5;
    int wm0 = wid * 16;
    float acc[8][4] = {};
    const __half* Ag = attn16 + ((size_t)bh * Ll + q0) * Ll;
    const __half* Vg = qkv + (size_t)b * Ll * D3 + 2 * Dd + h * HD;
    for (int t0 = 0; t0 < Ll; t0 += 64) {
        #pragma unroll
        for (int i = 0; i < 4; i++) {
            int t = tid + i * 256;
            int r = t >> 3, s = t & 7;
            *(uint4*)&As[r][s * 8] = *(const uint4*)(Ag + (size_t)r * Ll + t0 + s * 8);
        }
        #pragma unroll
        for (int i = 0; i < 2; i++) {
            int t = tid + i * 256;
            int r = t >> 3, s = t & 7;
            *(uint4*)&Vs[r][s * 8] = *(const uint4*)(Vg + (size_t)(t0 + r) * D3 + s * 8);
        }
        __syncthreads();
        #pragma unroll
        for (int ks = 0; ks < 64; ks += 16) {
            uint32_t a[4], bfr[8][2];
            ldsm_x4(a[0], a[1], a[2], a[3],
                    sm32(&As[wm0 + (lane & 15)][ks + (lane >> 4) * 8]));
            #pragma unroll
            for (int j = 0; j < 8; j++)
                ldsm_x2t(bfr[j][0], bfr[j][1], sm32(&Vs[ks + (lane & 15)][j * 8]));
            #pragma unroll
            for (int j = 0; j < 8; j++) mma16(acc[j], a, bfr[j]);
        }
        __syncthreads();
    }
    #pragma unroll
    for (int j = 0; j < 8; j++) {
        int q = q0 + wm0 + (lane >> 2);
        int c = j * 8 + (lane & 3) * 2;
        __half* dst = o16 + (size_t)(b * Ll + q) * Dd + h * HD + c;
        dst[0] = __float2half(acc[j][0]);
        dst[1] = __float2half(acc[j][1]);
        dst += (size_t)8 * Dd;
        dst[0] = __float2half(acc[j][2]);
        dst[1] = __float2half(acc[j][3]);
    }
}

// ---------------- FFN-in GEMM with fused GEGLU: F = gelu(A@Wb + bb) * (A@Wa + ba) ----------------
// BM=128, 64 cols per half. Grid (DH/64, BL/128).
__global__ void gemm_geglu_kernel(const __half* __restrict__ A, const __half* __restrict__ W,
                                  const float* __restrict__ bias, __half* __restrict__ F) {
    __shared__ __half As[128][40];
    __shared__ __half Bs[2][32][72];
    int bm = blockIdx.y * 128, bn = blockIdx.x * 64;
    int tid = threadIdx.x, lane = tid & 31, wid = tid >> 5;
    int wm = (wid >> 1) * 32, wn = (wid & 1) * 32;
    float acc[2][2][4][4] = {};   // [half][mi][nj][c]
    for (int k0 = 0; k0 < Dd; k0 += 32) {
        #pragma unroll
        for (int i = 0; i < 2; i++) {
            int t = tid + i * 256;
            int r = t >> 2, s = t & 3;
            *(uint4*)&As[r][s * 8] = *(const uint4*)(A + (size_t)(bm + r) * Dd + k0 + s * 8);
        }
        {
            int r = tid >> 3, s = tid & 7;
            #pragma unroll
            for (int hh = 0; hh < 2; hh++)
                *(uint4*)&Bs[hh][r][s * 8] =
                    *(const uint4*)(W + (size_t)(k0 + r) * (2 * DH) + bn + hh * DH + s * 8);
        }
        __syncthreads();
        #pragma unroll
        for (int ks = 0; ks < 32; ks += 16) {
            uint32_t a[2][4];
            #pragma unroll
            for (int mi = 0; mi < 2; mi++)
                ldsm_x4(a[mi][0], a[mi][1], a[mi][2], a[mi][3],
                        sm32(&As[wm + mi * 16 + (lane & 15)][ks + (lane >> 4) * 8]));
            #pragma unroll
            for (int hh = 0; hh < 2; hh++)
                #pragma unroll
                for (int nj = 0; nj < 4; nj++) {
                    uint32_t bfr[2];
                    ldsm_x2t(bfr[0], bfr[1], sm32(&Bs[hh][ks + (lane & 15)][wn + nj * 8]));
                    #pragma unroll
                    for (int mi = 0; mi < 2; mi++) mma16(acc[hh][mi][nj], a[mi], bfr);
                }
        }
        __syncthreads();
    }
    #pragma unroll
    for (int mi = 0; mi < 2; mi++) {
        #pragma unroll
        for (int nj = 0; nj < 4; nj++) {
            int r = bm + wm + mi * 16 + (lane >> 2);
            int c = bn + wn + nj * 8 + (lane & 3) * 2;
            float ba0 = bias[c], ba1 = bias[c + 1];
            float bb0 = bias[c + DH], bb1 = bias[c + DH + 1];
            #pragma unroll
            for (int hh = 0; hh < 2; hh++) {
                float av0 = acc[0][mi][nj][hh * 2]     + ba0;
                float av1 = acc[0][mi][nj][hh * 2 + 1] + ba1;
                float bg0 = acc[1][mi][nj][hh * 2]     + bb0;
                float bg1 = acc[1][mi][nj][hh * 2 + 1] + bb1;
                float g0 = 0.5f * bg0 * (1.0f + erff(bg0 * 0.70710678118654752f));
                float g1 = 0.5f * bg1 * (1.0f + erff(bg1 * 0.70710678118654752f));
                size_t idx = (size_t)(r + hh * 8) * DH + c;
                F[idx]     = __float2half(g0 * av0);
                F[idx + 1] = __float2half(g1 * av1);
            }
        }
    }
}

extern "C" void kernel_launch(void* const* d_in, const int* in_sizes, int n_in,
                              void* d_out, int out_size) {
    const float* x        = (const float*)d_in[0];
    const float* ln1_w    = (const float*)d_in[1];
    const float* ln1_b    = (const float*)d_in[2];
    const float* qkv_w    = (const float*)d_in[3];
    const float* qkv_b    = (const float*)d_in[4];
    const float* out_w    = (const float*)d_in[5];
    const float* out_b    = (const float*)d_in[6];
    const float* rel_bias = (const float*)d_in[7];
    const float* gamma1   = (const float*)d_in[8];
    const float* ln2_w    = (const float*)d_in[9];
    const float* ln2_b    = (const float*)d_in[10];
    const float* ffn_in_w = (const float*)d_in[11];
    const float* ffn_in_b = (const float*)d_in[12];
    const float* ffn_out_w= (const float*)d_in[13];
    const float* ffn_out_b= (const float*)d_in[14];
    const float* gamma2   = (const float*)d_in[15];

    float* out_x = (float*)d_out;
    float* attn  = (float*)d_out + XSIZE;

    __half *h16, *qkv16, *o16, *f16, *attn16, *w16;
    float *x1;
    float2 *stats;
    cudaGetSymbolAddress((void**)&h16,    g_h16);
    cudaGetSymbolAddress((void**)&qkv16,  g_qkv16);
    cudaGetSymbolAddress((void**)&o16,    g_o16);
    cudaGetSymbolAddress((void**)&f16,    g_f16);
    cudaGetSymbolAddress((void**)&attn16, g_attn16);
    cudaGetSymbolAddress((void**)&w16,    g_w16);
    cudaGetSymbolAddress((void**)&x1,     g_x1);
    cudaGetSymbolAddress((void**)&stats,  g_stats);

    // 0. convert weights to fp16 (vectorized)
    f2h_kernel<<<(int)(((long long)Dd * D3 / 4 + 255) / 256), 256>>>((const float4*)qkv_w,    (__half2*)(w16 + OFF_QKVW),   (long long)Dd * D3 / 4);
    f2h_kernel<<<(int)(((long long)Dd * Dd / 4 + 255) / 256), 256>>>((const float4*)out_w,    (__half2*)(w16 + OFF_OUTW),   (long long)Dd * Dd / 4);
    f2h_kernel<<<(int)(((long long)Dd * 2 * DH / 4 + 255) / 256), 256>>>((const float4*)ffn_in_w, (__half2*)(w16 + OFF_FFNIN), (long long)Dd * 2 * DH / 4);
    f2h_kernel<<<(int)(((long long)DH * Dd / 4 + 255) / 256), 256>>>((const float4*)ffn_out_w, (__half2*)(w16 + OFF_FFNOUT), (long long)DH * Dd / 4);

    // 1. h16 = LN1(x)
    ln_kernel<<<BL, 256>>>(x, ln1_w, ln1_b, h16);
    // 2. qkv16 = h16 @ qkv_w + qkv_b
    gemm16_kernel<0><<<dim3(D3 / 128, BL / 128), 256>>>(h16, w16 + OFF_QKVW, qkv_b, qkv16, nullptr, nullptr, nullptr, D3, Dd);
    // 3. S1: softmax stats
    stats_kernel<<<dim3(Ll / 128, Bb * Hh), 256>>>(qkv16, rel_bias, stats);
    // 4. S2: emit probabilities (fp32 -> d_out, fp16 -> attn16)
    emit_kernel<<<dim3(Ll / 128, Ll / 128, Bb * Hh), 256>>>(qkv16, rel_bias, stats, attn, attn16);
    // 5. o16 = attn16 @ v16
    av16_kernel<<<dim3(Ll / 128, 1, Bb * Hh), 256>>>(attn16, qkv16, o16);
    // 6. x1 = x + (o16 @ out_w + out_b) * gamma1   (fused epilogue)
    gemm16_kernel<1><<<dim3(Dd / 128, BL / 128), 256>>>(o16, w16 + OFF_OUTW, out_b, nullptr, x1, x, gamma1, Dd, Dd);
    // 7. h16 = LN2(x1)
    ln_kernel<<<BL, 256>>>(x1, ln2_w, ln2_b, h16);
    // 8. f16 = geglu(h16 @ ffn_in_w + b)   (fused)
    gemm_geglu_kernel<<<dim3(DH / 64, BL / 128), 256>>>(h16, w16 + OFF_FFNIN, ffn_in_b, f16);
    // 9. out_x = x1 + (f16 @ ffn_out_w + b) * gamma2   (fused epilogue)
    gemm16_kernel<1><<<dim3(Dd / 128, BL / 128), 256>>>(f16, w16 + OFF_FFNOUT, ffn_out_b, nullptr, out_x, x1, gamma2, Dd, DH);
}

// round 4
// speedup vs baseline: 1.4690x; 1.4690x over previous
#include <cuda_runtime.h>
#include <cuda_fp16.h>
#include <math.h>
#include <stdint.h>

// Problem constants
constexpr int Bb  = 2;
constexpr int Ll  = 2048;
constexpr int Dd  = 512;
constexpr int Hh  = 8;
constexpr int HD  = 64;
constexpr int DH  = 2048;
constexpr int MREL = 128;
constexpr int D3  = 3 * Dd;    // 1536
constexpr int BL  = Bb * Ll;   // 4096
constexpr long long XSIZE  = (long long)BL * Dd;
constexpr long long ATTN_N = (long long)Bb * Hh * Ll * Ll;  // 67,108,864

// fp16 staging buffers
__device__ __half g_h16  [BL * Dd];
__device__ __half g_qkv16[BL * D3];
__device__ __half g_o16  [BL * Dd];
__device__ __half g_f16  [BL * DH];
__device__ __half g_attn16[ATTN_N];   // scores (pre-softmax) then probs, fp16
// fp16 weights: qkv_w | out_w | ffn_in_w | ffn_out_w  (contiguous)
constexpr long long OFF_QKVW   = 0;
constexpr long long OFF_OUTW   = OFF_QKVW  + (long long)Dd * D3;
constexpr long long OFF_FFNIN  = OFF_OUTW  + (long long)Dd * Dd;
constexpr long long OFF_FFNOUT = OFF_FFNIN + (long long)Dd * 2 * DH;
constexpr long long W16_TOTAL  = OFF_FFNOUT + (long long)DH * Dd;   // 4,194,304
__device__ __half g_w16[W16_TOTAL];
__device__ float  g_x1 [BL * Dd];

// ---------------- helpers ----------------
static __device__ __forceinline__ uint32_t sm32(const void* p) {
    return (uint32_t)__cvta_generic_to_shared(p);
}
static __device__ __forceinline__ void cp16(void* dst, const void* src) {
    asm volatile("cp.async.cg.shared.global [%0], [%1], 16;\n"
                 :: "r"(sm32(dst)), "l"(__cvta_generic_to_global(src)));
}
static __device__ __forceinline__ void cp_commit() {
    asm volatile("cp.async.commit_group;\n");
}
template <int N> static __device__ __forceinline__ void cp_wait() {
    asm volatile("cp.async.wait_group %0;\n" :: "n"(N));
}
static __device__ __forceinline__ void ldsm_x4(uint32_t& r0, uint32_t& r1, uint32_t& r2, uint32_t& r3, uint32_t a) {
    asm volatile("ldmatrix.sync.aligned.m8n8.x4.shared.b16 {%0,%1,%2,%3}, [%4];\n"
                 : "=r"(r0), "=r"(r1), "=r"(r2), "=r"(r3) : "r"(a));
}
static __device__ __forceinline__ void ldsm_x2(uint32_t& r0, uint32_t& r1, uint32_t a) {
    asm volatile("ldmatrix.sync.aligned.m8n8.x2.shared.b16 {%0,%1}, [%2];\n"
                 : "=r"(r0), "=r"(r1) : "r"(a));
}
static __device__ __forceinline__ void ldsm_x2t(uint32_t& r0, uint32_t& r1, uint32_t a) {
    asm volatile("ldmatrix.sync.aligned.m8n8.x2.trans.shared.b16 {%0,%1}, [%2];\n"
                 : "=r"(r0), "=r"(r1) : "r"(a));
}
static __device__ __forceinline__ void mma16(float* c, const uint32_t* a, const uint32_t* b) {
    asm volatile("mma.sync.aligned.m16n8k16.row.col.f32.f16.f16.f32 "
                 "{%0,%1,%2,%3}, {%4,%5,%6,%7}, {%8,%9}, {%0,%1,%2,%3};\n"
                 : "+f"(c[0]), "+f"(c[1]), "+f"(c[2]), "+f"(c[3])
                 : "r"(a[0]), "r"(a[1]), "r"(a[2]), "r"(a[3]), "r"(b[0]), "r"(b[1]));
}
static __device__ __forceinline__ int clampq(int d) {
    return d < -(MREL - 1) ? -(MREL - 1) : (d > (MREL - 1) ? (MREL - 1) : d);
}

// ---------------- all weights fp32 -> fp16, one launch ----------------
constexpr long long E0 = OFF_OUTW   / 4;   // 196608
constexpr long long E1 = OFF_FFNIN  / 4;   // 262144
constexpr long long E2 = OFF_FFNOUT / 4;   // 786432
constexpr long long E3 = W16_TOTAL  / 4;   // 1048576
__global__ void f2h_all_kernel(const float4* __restrict__ a, const float4* __restrict__ b,
                               const float4* __restrict__ c, const float4* __restrict__ d,
                               __half2* __restrict__ dst) {
    long long i = (long long)blockIdx.x * 256 + threadIdx.x;
    const float4* src; long long off;
    if (i < E0)      { src = a; off = 0;  }
    else if (i < E1) { src = b; off = E0; }
    else if (i < E2) { src = c; off = E1; }
    else             { src = d; off = E2; }
    float4 v = src[i - off];
    dst[i * 2]     = __floats2half2_rn(v.x, v.y);
    dst[i * 2 + 1] = __floats2half2_rn(v.z, v.w);
}

// ---------------- LayerNorm -> fp16 out ----------------
__global__ void ln_kernel(const float* __restrict__ x, const float* __restrict__ w,
                          const float* __restrict__ b, __half* __restrict__ out) {
    int row = blockIdx.x;
    const float* xr = x + (long long)row * Dd;
    int t = threadIdx.x; // 256
    float v0 = xr[t], v1 = xr[t + 256];
    __shared__ float red[256];
    red[t] = v0 + v1;
    __syncthreads();
    #pragma unroll
    for (int o = 128; o > 0; o >>= 1) { if (t < o) red[t] += red[t + o]; __syncthreads(); }
    float mu = red[0] * (1.0f / Dd);
    __syncthreads();
    float d0 = v0 - mu, d1 = v1 - mu;
    red[t] = d0 * d0 + d1 * d1;
    __syncthreads();
    #pragma unroll
    for (int o = 128; o > 0; o >>= 1) { if (t < o) red[t] += red[t + o]; __syncthreads(); }
    float rstd = rsqrtf(red[0] * (1.0f / Dd) + 1e-5f);
    __half* orow = out + (long long)row * Dd;
    orow[t]       = __float2half(d0 * rstd * w[t]       + b[t]);
    orow[t + 256] = __float2half(d1 * rstd * w[t + 256] + b[t + 256]);
}

// ---------------- Tensor-core GEMM, cp.async double-buffered ----------------
// BM=128 BN=128 BK=32, 256 threads. MODE 0: half out = acc+bias.
// MODE 1: float out = resid + (acc+bias)*gamma.
template <int MODE>
__global__ void gemm16_kernel(const __half* __restrict__ A, const __half* __restrict__ W,
                              const float* __restrict__ bias, __half* __restrict__ Ch,
                              float* __restrict__ Cf, const float* __restrict__ resid,
                              const float* __restrict__ gamma, int N, int K) {
    __shared__ __half As[2][128][40];
    __shared__ __half Bs[2][32][136];
    int bm = blockIdx.y * 128, bn = blockIdx.x * 128;
    int tid = threadIdx.x, lane = tid & 31, wid = tid >> 5;
    int wm0 = (wid & 1) * 64, wn0 = (wid >> 1) * 32;

    auto load = [&](int k0, int st) {
        #pragma unroll
        for (int i = 0; i < 2; i++) {
            int t = tid + i * 256;
            int r = t >> 2, s = t & 3;
            cp16(&As[st][r][s * 8], A + (size_t)(bm + r) * K + k0 + s * 8);
        }
        #pragma unroll
        for (int i = 0; i < 2; i++) {
            int t = tid + i * 256;
            int r = t >> 4, s = t & 15;
            cp16(&Bs[st][r][s * 8], W + (size_t)(k0 + r) * N + bn + s * 8);
        }
    };
    load(0, 0); cp_commit();
    float acc[4][4][4] = {};
    int nIter = K / 32;
    for (int it = 0; it < nIter; it++) {
        int cur = it & 1;
        if (it + 1 < nIter) { load((it + 1) * 32, cur ^ 1); cp_commit(); cp_wait<1>(); }
        else cp_wait<0>();
        __syncthreads();
        #pragma unroll
        for (int ks = 0; ks < 32; ks += 16) {
            uint32_t a[4][4], b[4][2];
            #pragma unroll
            for (int i = 0; i < 4; i++)
                ldsm_x4(a[i][0], a[i][1], a[i][2], a[i][3],
                        sm32(&As[cur][wm0 + i * 16 + (lane & 15)][ks + (lane >> 4) * 8]));
            #pragma unroll
            for (int j = 0; j < 4; j++)
                ldsm_x2t(b[j][0], b[j][1], sm32(&Bs[cur][ks + (lane & 15)][wn0 + j * 8]));
            #pragma unroll
            for (int i = 0; i < 4; i++)
                #pragma unroll
                for (int j = 0; j < 4; j++) mma16(acc[i][j], a[i], b[j]);
        }
        __syncthreads();
    }
    #pragma unroll
    for (int i = 0; i < 4; i++) {
        #pragma unroll
        for (int j = 0; j < 4; j++) {
            int r = bm + wm0 + i * 16 + (lane >> 2);
            int c = bn + wn0 + j * 8 + (lane & 3) * 2;
            #pragma unroll
            for (int hh = 0; hh < 2; hh++) {
                size_t idx = (size_t)(r + hh * 8) * N + c;
                float v0 = acc[i][j][hh * 2]     + bias[c];
                float v1 = acc[i][j][hh * 2 + 1] + bias[c + 1];
                if (MODE == 0) {
                    *(__half2*)(Ch + idx) = __floats2half2_rn(v0, v1);
                } else {
                    float2 rv = *(const float2*)(resid + idx);
                    float2 ov = make_float2(rv.x + v0 * gamma[c], rv.y + v1 * gamma[c + 1]);
                    *(float2*)(Cf + idx) = ov;
                }
            }
        }
    }
}

// ---------------- Scores: S = scale*(Q K^T) + rel_bias -> fp16 scores ----------------
// Block: 128q x 128k per (b,h). 8 warps: warp_m {0..3} x warp_n {0,1}.
__global__ void score16_kernel(const __half* __restrict__ qkv, const float* __restrict__ rel_bias,
                               __half* __restrict__ s16) {
    int bh = blockIdx.z, b = bh >> 3, h = bh & 7;
    int q0 = blockIdx.y * 128, k0 = blockIdx.x * 128;
    __shared__ __half Qs[128][72];
    __shared__ __half Ks[128][72];
    __shared__ float rb_s[2 * MREL - 1];
    int tid = threadIdx.x, lane = tid & 31, wid = tid >> 5;
    if (tid < 2 * MREL - 1) rb_s[tid] = rel_bias[h * (2 * MREL - 1) + tid];
    const __half* Qg = qkv + (size_t)b * Ll * D3 + h * HD;
    const __half* Kg = Qg + Dd;
    #pragma unroll
    for (int i = 0; i < 4; i++) {
        int t = tid + i * 256;
        int r = t >> 3, s = t & 7;
        *(uint4*)&Qs[r][s * 8] = *(const uint4*)(Qg + (size_t)(q0 + r) * D3 + s * 8);
        *(uint4*)&Ks[r][s * 8] = *(const uint4*)(Kg + (size_t)(k0 + r) * D3 + s * 8);
    }
    __syncthreads();
    int wm0 = (wid >> 1) * 32, wn0 = (wid & 1) * 64;
    float acc[2][8][4] = {};
    #pragma unroll
    for (int ks = 0; ks < 64; ks += 16) {
        uint32_t a[2][4], bfr[8][2];
        #pragma unroll
        for (int i = 0; i < 2; i++)
            ldsm_x4(a[i][0], a[i][1], a[i][2], a[i][3],
                    sm32(&Qs[wm0 + i * 16 + (lane & 15)][ks + (lane >> 4) * 8]));
        #pragma unroll
        for (int j = 0; j < 8; j++)
            ldsm_x2(bfr[j][0], bfr[j][1],
                    sm32(&Ks[wn0 + j * 8 + (lane & 7)][ks + ((lane >> 3) & 1) * 8]));
        #pragma unroll
        for (int i = 0; i < 2; i++)
            #pragma unroll
            for (int j = 0; j < 8; j++) mma16(acc[i][j], a[i], bfr[j]);
    }
    const float scale = 0.125f;
    #pragma unroll
    for (int i = 0; i < 2; i++) {
        #pragma unroll
        for (int j = 0; j < 8; j++) {
            #pragma unroll
            for (int half_ = 0; half_ < 2; half_++) {
                int qq = q0 + wm0 + i * 16 + (lane >> 2) + half_ * 8;
                size_t row = ((size_t)bh * Ll + qq) * Ll;
                int kk = k0 + wn0 + j * 8 + (lane & 3) * 2;
                float s0 = acc[i][j][half_ * 2]     * scale + rb_s[clampq(qq - kk)     + MREL - 1];
                float s1 = acc[i][j][half_ * 2 + 1] * scale + rb_s[clampq(qq - kk - 1) + MREL - 1];
                *(__half2*)(s16 + row + kk) = __floats2half2_rn(s0, s1);
            }
        }
    }
}

// ---------------- Softmax: read fp16 scores, write fp32 probs (d_out) + fp16 in place ----------------
__global__ void softmax_kernel(__half* __restrict__ s16, float* __restrict__ attn) {
    size_t row = blockIdx.x;
    uint4* r16 = reinterpret_cast<uint4*>(s16 + row * Ll);   // 256 uint4 per row
    float4* rf = reinterpret_cast<float4*>(attn + row * Ll); // 512 float4 per row
    int t = threadIdx.x;  // 256, one uint4 (8 halves) each
    uint4 v = r16[t];
    float2 p0 = __half22float2(*(__half2*)&v.x);
    float2 p1 = __half22float2(*(__half2*)&v.y);
    float2 p2 = __half22float2(*(__half2*)&v.z);
    float2 p3 = __half22float2(*(__half2*)&v.w);
    float f[8] = {p0.x, p0.y, p1.x, p1.y, p2.x, p2.y, p3.x, p3.y};
    float m = f[0];
    #pragma unroll
    for (int i = 1; i < 8; i++) m = fmaxf(m, f[i]);
    __shared__ float red[256];
    red[t] = m;
    __syncthreads();
    #pragma unroll
    for (int o = 128; o > 0; o >>= 1) { if (t < o) red[t] = fmaxf(red[t], red[t + o]); __syncthreads(); }
    float rowmax = red[0];
    __syncthreads();
    float s = 0.f;
    #pragma unroll
    for (int i = 0; i < 8; i++) { f[i] = __expf(f[i] - rowmax); s += f[i]; }
    red[t] = s;
    __syncthreads();
    #pragma unroll
    for (int o = 128; o > 0; o >>= 1) { if (t < o) red[t] += red[t + o]; __syncthreads(); }
    float inv = 1.0f / red[0];
    #pragma unroll
    for (int i = 0; i < 8; i++) f[i] *= inv;
    rf[t * 2]     = make_float4(f[0], f[1], f[2], f[3]);
    rf[t * 2 + 1] = make_float4(f[4], f[5], f[6], f[7]);
    uint4 o16;
    *(__half2*)&o16.x = __floats2half2_rn(f[0], f[1]);
    *(__half2*)&o16.y = __floats2half2_rn(f[2], f[3]);
    *(__half2*)&o16.z = __floats2half2_rn(f[4], f[5]);
    *(__half2*)&o16.w = __floats2half2_rn(f[6], f[7]);
    r16[t] = o16;
}

// ---------------- AV: o16 = P @ V, cp.async double-buffered, BK=32 ----------------
__global__ void av16_kernel(const __half* __restrict__ attn16, const __half* __restrict__ qkv,
                            __half* __restrict__ o16) {
    int bh = blockIdx.z, b = bh >> 3, h = bh & 7;
    int q0 = blockIdx.x * 128;
    __shared__ __half As[2][128][40];
    __shared__ __half Vs[2][32][72];
    int tid = threadIdx.x, lane = tid & 31, wid = tid >> 5;
    int wm0 = wid * 16;
    float acc[8][4] = {};
    const __half* Ag = attn16 + ((size_t)bh * Ll + q0) * Ll;
    const __half* Vg = qkv + (size_t)b * Ll * D3 + 2 * Dd + h * HD;
    auto load = [&](int t0, int st) {
        #pragma unroll
        for (int i = 0; i < 2; i++) {
            int t = tid + i * 256;
            int r = t >> 2, s = t & 3;
            cp16(&As[st][r][s * 8], Ag + (size_t)r * Ll + t0 + s * 8);
        }
        {
            int r = tid >> 3, s = tid & 7;
            cp16(&Vs[st][r][s * 8], Vg + (size_t)(t0 + r) * D3 + s * 8);
        }
    };
    load(0, 0); cp_commit();
    constexpr int NIT = Ll / 32;
    for (int it = 0; it < NIT; it++) {
        int cur = it & 1;
        if (it + 1 < NIT) { load((it + 1) * 32, cur ^ 1); cp_commit(); cp_wait<1>(); }
        else cp_wait<0>();
        __syncthreads();
        #pragma unroll
        for (int ks = 0; ks < 32; ks += 16) {
            uint32_t a[4], bfr[8][2];
            ldsm_x4(a[0], a[1], a[2], a[3],
                    sm32(&As[cur][wm0 + (lane & 15)][ks + (lane >> 4) * 8]));
            #pragma unroll
            for (int j = 0; j < 8; j++)
                ldsm_x2t(bfr[j][0], bfr[j][1], sm32(&Vs[cur][ks + (lane & 15)][j * 8]));
            #pragma unroll
            for (int j = 0; j < 8; j++) mma16(acc[j], a, bfr[j]);
        }
        __syncthreads();
    }
    #pragma unroll
    for (int j = 0; j < 8; j++) {
        int q = q0 + wm0 + (lane >> 2);
        int c = j * 8 + (lane & 3) * 2;
        __half* dst = o16 + (size_t)(b * Ll + q) * Dd + h * HD + c;
        *(__half2*)dst = __floats2half2_rn(acc[j][0], acc[j][1]);
        *(__half2*)(dst + (size_t)8 * Dd) = __floats2half2_rn(acc[j][2], acc[j][3]);
    }
}

// ---------------- FFN-in GEMM + fused GEGLU, cp.async double-buffered ----------------
__global__ void gemm_geglu_kernel(const __half* __restrict__ A, const __half* __restrict__ W,
                                  const float* __restrict__ bias, __half* __restrict__ F) {
    __shared__ __half As[2][128][40];
    __shared__ __half Bs[2][2][32][72];
    int bm = blockIdx.y * 128, bn = blockIdx.x * 64;
    int tid = threadIdx.x, lane = tid & 31, wid = tid >> 5;
    int wm = (wid >> 1) * 32, wn = (wid & 1) * 32;
    float acc[2][2][4][4] = {};
    auto load = [&](int k0, int st) {
        #pragma unroll
        for (int i = 0; i < 2; i++) {
            int t = tid + i * 256;
            int r = t >> 2, s = t & 3;
            cp16(&As[st][r][s * 8], A + (size_t)(bm + r) * Dd + k0 + s * 8);
        }
        {
            int r = tid >> 3, s = tid & 7;
            #pragma unroll
            for (int hh = 0; hh < 2; hh++)
                cp16(&Bs[st][hh][r][s * 8],
                     W + (size_t)(k0 + r) * (2 * DH) + bn + hh * DH + s * 8);
        }
    };
    load(0, 0); cp_commit();
    constexpr int NIT = Dd / 32;
    for (int it = 0; it < NIT; it++) {
        int cur = it & 1;
        if (it + 1 < NIT) { load((it + 1) * 32, cur ^ 1); cp_commit(); cp_wait<1>(); }
        else cp_wait<0>();
        __syncthreads();
        #pragma unroll
        for (int ks = 0; ks < 32; ks += 16) {
            uint32_t a[2][4];
            #pragma unroll
            for (int mi = 0; mi < 2; mi++)
                ldsm_x4(a[mi][0], a[mi][1], a[mi][2], a[mi][3],
                        sm32(&As[cur][wm + mi * 16 + (lane & 15)][ks + (lane >> 4) * 8]));
            #pragma unroll
            for (int hh = 0; hh < 2; hh++)
                #pragma unroll
                for (int nj = 0; nj < 4; nj++) {
                    uint32_t bfr[2];
                    ldsm_x2t(bfr[0], bfr[1], sm32(&Bs[cur][hh][ks + (lane & 15)][wn + nj * 8]));
                    #pragma unroll
                    for (int mi = 0; mi < 2; mi++) mma16(acc[hh][mi][nj], a[mi], bfr);
                }
        }
        __syncthreads();
    }
    #pragma unroll
    for (int mi = 0; mi < 2; mi++) {
        #pragma unroll
        for (int nj = 0; nj < 4; nj++) {
            int r = bm + wm + mi * 16 + (lane >> 2);
            int c = bn + wn + nj * 8 + (lane & 3) * 2;
            float ba0 = bias[c], ba1 = bias[c + 1];
            float bb0 = bias[c + DH], bb1 = bias[c + DH + 1];
            #pragma unroll
            for (int hh = 0; hh < 2; hh++) {
                float av0 = acc[0][mi][nj][hh * 2]     + ba0;
                float av1 = acc[0][mi][nj][hh * 2 + 1] + ba1;
                float bg0 = acc[1][mi][nj][hh * 2]     + bb0;
                float bg1 = acc[1][mi][nj][hh * 2 + 1] + bb1;
                float g0 = 0.5f * bg0 * (1.0f + erff(bg0 * 0.70710678118654752f));
                float g1 = 0.5f * bg1 * (1.0f + erff(bg1 * 0.70710678118654752f));
                size_t idx = (size_t)(r + hh * 8) * DH + c;
                *(__half2*)(F + idx) = __floats2half2_rn(g0 * av0, g1 * av1);
            }
        }
    }
}

extern "C" void kernel_launch(void* const* d_in, const int* in_sizes, int n_in,
                              void* d_out, int out_size) {
    const float* x        = (const float*)d_in[0];
    const float* ln1_w    = (const float*)d_in[1];
    const float* ln1_b    = (const float*)d_in[2];
    const float* qkv_w    = (const float*)d_in[3];
    const float* qkv_b    = (const float*)d_in[4];
    const float* out_w    = (const float*)d_in[5];
    const float* out_b    = (const float*)d_in[6];
    const float* rel_bias = (const float*)d_in[7];
    const float* gamma1   = (const float*)d_in[8];
    const float* ln2_w    = (const float*)d_in[9];
    const float* ln2_b    = (const float*)d_in[10];
    const float* ffn_in_w = (const float*)d_in[11];
    const float* ffn_in_b = (const float*)d_in[12];
    const float* ffn_out_w= (const float*)d_in[13];
    const float* ffn_out_b= (const float*)d_in[14];
    const float* gamma2   = (const float*)d_in[15];

    float* out_x = (float*)d_out;
    float* attn  = (float*)d_out + XSIZE;

    __half *h16, *qkv16, *o16, *f16, *attn16, *w16;
    float *x1;
    cudaGetSymbolAddress((void**)&h16,    g_h16);
    cudaGetSymbolAddress((void**)&qkv16,  g_qkv16);
    cudaGetSymbolAddress((void**)&o16,    g_o16);
    cudaGetSymbolAddress((void**)&f16,    g_f16);
    cudaGetSymbolAddress((void**)&attn16, g_attn16);
    cudaGetSymbolAddress((void**)&w16,    g_w16);
    cudaGetSymbolAddress((void**)&x1,     g_x1);

    // 0. convert all weights to fp16 in one launch
    f2h_all_kernel<<<(int)(E3 / 256), 256>>>((const float4*)qkv_w, (const float4*)out_w,
                                             (const float4*)ffn_in_w, (const float4*)ffn_out_w,
                                             (__half2*)w16);
    // 1. h16 = LN1(x)
    ln_kernel<<<BL, 256>>>(x, ln1_w, ln1_b, h16);
    // 2. qkv16 = h16 @ qkv_w + qkv_b
    gemm16_kernel<0><<<dim3(D3 / 128, BL / 128), 256>>>(h16, w16 + OFF_QKVW, qkv_b, qkv16, nullptr, nullptr, nullptr, D3, Dd);
    // 3. fp16 scores -> attn16 buffer
    score16_kernel<<<dim3(Ll / 128, Ll / 128, Bb * Hh), 256>>>(qkv16, rel_bias, attn16);
    // 4. softmax: fp32 probs -> d_out, fp16 probs in place
    softmax_kernel<<<Bb * Hh * Ll, 256>>>(attn16, attn);
    // 5. o16 = P @ V
    av16_kernel<<<dim3(Ll / 128, 1, Bb * Hh), 256>>>(attn16, qkv16, o16);
    // 6. x1 = x + (o16 @ out_w + out_b) * gamma1
    gemm16_kernel<1><<<dim3(Dd / 128, BL / 128), 256>>>(o16, w16 + OFF_OUTW, out_b, nullptr, x1, x, gamma1, Dd, Dd);
    // 7. h16 = LN2(x1)
    ln_kernel<<<BL, 256>>>(x1, ln2_w, ln2_b, h16);
    // 8. f16 = geglu(h16 @ ffn_in_w + b)
    gemm_geglu_kernel<<<dim3(DH / 64, BL / 128), 256>>>(h16, w16 + OFF_FFNIN, ffn_in_b, f16);
    // 9. out_x = x1 + (f16 @ ffn_out_w + b) * gamma2
    gemm16_kernel<1><<<dim3(Dd / 128, BL / 128), 256>>>(f16, w16 + OFF_FFNOUT, ffn_out_b, nullptr, out_x, x1, gamma2, Dd, DH);
}

// round 5
// speedup vs baseline: 1.5740x; 1.0715x over previous
#include <cuda_runtime.h>
#include <cuda_fp16.h>
#include <math.h>
#include <stdint.h>

// Problem constants
constexpr int Bb  = 2;
constexpr int Ll  = 2048;
constexpr int Dd  = 512;
constexpr int Hh  = 8;
constexpr int HD  = 64;
constexpr int DH  = 2048;
constexpr int MREL = 128;
constexpr int D3  = 3 * Dd;    // 1536
constexpr int BL  = Bb * Ll;   // 4096
constexpr long long XSIZE  = (long long)BL * Dd;
constexpr long long ATTN_N = (long long)Bb * Hh * Ll * Ll;  // 67,108,864
constexpr int NROWS = Bb * Hh * Ll;        // 32768 attention rows
constexpr int KTILES = Ll / 128;           // 16

// fp16 staging buffers
__device__ __half g_h16  [BL * Dd];
__device__ __half g_qkv16[BL * D3];
__device__ __half g_o16  [BL * Dd];
__device__ __half g_f16  [BL * DH];
__device__ __half g_attn16[ATTN_N];   // fp16 scores (pre-softmax)
// fp16 weights: qkv_w | out_w | ffn_in_w | ffn_out_w  (contiguous)
constexpr long long OFF_QKVW   = 0;
constexpr long long OFF_OUTW   = OFF_QKVW  + (long long)Dd * D3;
constexpr long long OFF_FFNIN  = OFF_OUTW  + (long long)Dd * Dd;
constexpr long long OFF_FFNOUT = OFF_FFNIN + (long long)Dd * 2 * DH;
constexpr long long W16_TOTAL  = OFF_FFNOUT + (long long)DH * Dd;   // 4,194,304
__device__ __half g_w16[W16_TOTAL];
__device__ float  g_x1  [BL * Dd];
__device__ float  g_psum[(long long)NROWS * KTILES];  // per-(row, ktile) partial expsum
__device__ float  g_inv [NROWS];                      // 1/rowsum

// ---------------- helpers ----------------
static __device__ __forceinline__ uint32_t sm32(const void* p) {
    return (uint32_t)__cvta_generic_to_shared(p);
}
static __device__ __forceinline__ void cp16(void* dst, const void* src) {
    asm volatile("cp.async.cg.shared.global [%0], [%1], 16;\n"
                 :: "r"(sm32(dst)), "l"(__cvta_generic_to_global(src)));
}
static __device__ __forceinline__ void cp_commit() {
    asm volatile("cp.async.commit_group;\n");
}
template <int N> static __device__ __forceinline__ void cp_wait() {
    asm volatile("cp.async.wait_group %0;\n" :: "n"(N));
}
static __device__ __forceinline__ void ldsm_x4(uint32_t& r0, uint32_t& r1, uint32_t& r2, uint32_t& r3, uint32_t a) {
    asm volatile("ldmatrix.sync.aligned.m8n8.x4.shared.b16 {%0,%1,%2,%3}, [%4];\n"
                 : "=r"(r0), "=r"(r1), "=r"(r2), "=r"(r3) : "r"(a));
}
static __device__ __forceinline__ void ldsm_x4t(uint32_t& r0, uint32_t& r1, uint32_t& r2, uint32_t& r3, uint32_t a) {
    asm volatile("ldmatrix.sync.aligned.m8n8.x4.trans.shared.b16 {%0,%1,%2,%3}, [%4];\n"
                 : "=r"(r0), "=r"(r1), "=r"(r2), "=r"(r3) : "r"(a));
}
static __device__ __forceinline__ void ldsm_x2t(uint32_t& r0, uint32_t& r1, uint32_t a) {
    asm volatile("ldmatrix.sync.aligned.m8n8.x2.trans.shared.b16 {%0,%1}, [%2];\n"
                 : "=r"(r0), "=r"(r1) : "r"(a));
}
static __device__ __forceinline__ void mma16(float* c, const uint32_t* a, const uint32_t* b) {
    asm volatile("mma.sync.aligned.m16n8k16.row.col.f32.f16.f16.f32 "
                 "{%0,%1,%2,%3}, {%4,%5,%6,%7}, {%8,%9}, {%0,%1,%2,%3};\n"
                 : "+f"(c[0]), "+f"(c[1]), "+f"(c[2]), "+f"(c[3])
                 : "r"(a[0]), "r"(a[1]), "r"(a[2]), "r"(a[3]), "r"(b[0]), "r"(b[1]));
}
static __device__ __forceinline__ int clampq(int d) {
    return d < -(MREL - 1) ? -(MREL - 1) : (d > (MREL - 1) ? (MREL - 1) : d);
}

// ---------------- all weights fp32 -> fp16, one launch ----------------
constexpr long long E0 = OFF_OUTW   / 4;
constexpr long long E1 = OFF_FFNIN  / 4;
constexpr long long E2 = OFF_FFNOUT / 4;
constexpr long long E3 = W16_TOTAL  / 4;
__global__ void f2h_all_kernel(const float4* __restrict__ a, const float4* __restrict__ b,
                               const float4* __restrict__ c, const float4* __restrict__ d,
                               __half2* __restrict__ dst) {
    long long i = (long long)blockIdx.x * 256 + threadIdx.x;
    const float4* src; long long off;
    if (i < E0)      { src = a; off = 0;  }
    else if (i < E1) { src = b; off = E0; }
    else if (i < E2) { src = c; off = E1; }
    else             { src = d; off = E2; }
    float4 v = src[i - off];
    dst[i * 2]     = __floats2half2_rn(v.x, v.y);
    dst[i * 2 + 1] = __floats2half2_rn(v.z, v.w);
}

// ---------------- LayerNorm -> fp16 out ----------------
__global__ void ln_kernel(const float* __restrict__ x, const float* __restrict__ w,
                          const float* __restrict__ b, __half* __restrict__ out) {
    int row = blockIdx.x;
    const float* xr = x + (long long)row * Dd;
    int t = threadIdx.x; // 256
    float v0 = xr[t], v1 = xr[t + 256];
    __shared__ float red[256];
    red[t] = v0 + v1;
    __syncthreads();
    #pragma unroll
    for (int o = 128; o > 0; o >>= 1) { if (t < o) red[t] += red[t + o]; __syncthreads(); }
    float mu = red[0] * (1.0f / Dd);
    __syncthreads();
    float d0 = v0 - mu, d1 = v1 - mu;
    red[t] = d0 * d0 + d1 * d1;
    __syncthreads();
    #pragma unroll
    for (int o = 128; o > 0; o >>= 1) { if (t < o) red[t] += red[t + o]; __syncthreads(); }
    float rstd = rsqrtf(red[0] * (1.0f / Dd) + 1e-5f);
    __half* orow = out + (long long)row * Dd;
    orow[t]       = __float2half(d0 * rstd * w[t]       + b[t]);
    orow[t + 256] = __float2half(d1 * rstd * w[t + 256] + b[t + 256]);
}

// ---------------- Tensor-core GEMM, cp.async double-buffered ----------------
// MODE 0: half out = acc+bias.  MODE 1: float out = resid + (acc+bias)*gamma.
template <int MODE>
__global__ void gemm16_kernel(const __half* __restrict__ A, const __half* __restrict__ W,
                              const float* __restrict__ bias, __half* __restrict__ Ch,
                              float* __restrict__ Cf, const float* __restrict__ resid,
                              const float* __restrict__ gamma, int N, int K) {
    __shared__ __half As[2][128][40];
    __shared__ __half Bs[2][32][136];
    int bm = blockIdx.y * 128, bn = blockIdx.x * 128;
    int tid = threadIdx.x, lane = tid & 31, wid = tid >> 5;
    int wm0 = (wid & 1) * 64, wn0 = (wid >> 1) * 32;

    auto load = [&](int k0, int st) {
        #pragma unroll
        for (int i = 0; i < 2; i++) {
            int t = tid + i * 256;
            int r = t >> 2, s = t & 3;
            cp16(&As[st][r][s * 8], A + (size_t)(bm + r) * K + k0 + s * 8);
        }
        #pragma unroll
        for (int i = 0; i < 2; i++) {
            int t = tid + i * 256;
            int r = t >> 4, s = t & 15;
            cp16(&Bs[st][r][s * 8], W + (size_t)(k0 + r) * N + bn + s * 8);
        }
    };
    load(0, 0); cp_commit();
    float acc[4][4][4] = {};
    int nIter = K / 32;
    for (int it = 0; it < nIter; it++) {
        int cur = it & 1;
        if (it + 1 < nIter) { load((it + 1) * 32, cur ^ 1); cp_commit(); cp_wait<1>(); }
        else cp_wait<0>();
        __syncthreads();
        #pragma unroll
        for (int ks = 0; ks < 32; ks += 16) {
            uint32_t a[4][4], b[4][2];
            #pragma unroll
            for (int i = 0; i < 4; i++)
                ldsm_x4(a[i][0], a[i][1], a[i][2], a[i][3],
                        sm32(&As[cur][wm0 + i * 16 + (lane & 15)][ks + (lane >> 4) * 8]));
            #pragma unroll
            for (int j = 0; j < 4; j++)
                ldsm_x2t(b[j][0], b[j][1], sm32(&Bs[cur][ks + (lane & 15)][wn0 + j * 8]));
            #pragma unroll
            for (int i = 0; i < 4; i++)
                #pragma unroll
                for (int j = 0; j < 4; j++) mma16(acc[i][j], a[i], b[j]);
        }
        __syncthreads();
    }
    #pragma unroll
    for (int i = 0; i < 4; i++) {
        #pragma unroll
        for (int j = 0; j < 4; j++) {
            int r = bm + wm0 + i * 16 + (lane >> 2);
            int c = bn + wn0 + j * 8 + (lane & 3) * 2;
            #pragma unroll
            for (int hh = 0; hh < 2; hh++) {
                size_t idx = (size_t)(r + hh * 8) * N + c;
                float v0 = acc[i][j][hh * 2]     + bias[c];
                float v1 = acc[i][j][hh * 2 + 1] + bias[c + 1];
                if (MODE == 0) {
                    *(__half2*)(Ch + idx) = __floats2half2_rn(v0, v1);
                } else {
                    float2 rv = *(const float2*)(resid + idx);
                    float2 ov = make_float2(rv.x + v0 * gamma[c], rv.y + v1 * gamma[c + 1]);
                    *(float2*)(Cf + idx) = ov;
                }
            }
        }
    }
}

// ---------------- Scores: S = scale*(Q K^T) + rel_bias -> fp16 scores + partial expsums --------
// Block: 128q x 128k per (b,h). 8 warps: warp_m {0..3} x warp_n {0,1}.
__global__ void score16_kernel(const __half* __restrict__ qkv, const float* __restrict__ rel_bias,
                               __half* __restrict__ s16, float* __restrict__ psum) {
    int bh = blockIdx.z, b = bh >> 3, h = bh & 7;
    int q0 = blockIdx.y * 128, k0 = blockIdx.x * 128;
    __shared__ __half Qs[128][72];
    __shared__ __half Ks[128][72];
    __shared__ float rb_s[2 * MREL - 1];
    __shared__ float psum_s[128][2];
    int tid = threadIdx.x, lane = tid & 31, wid = tid >> 5;
    if (tid < 2 * MREL - 1) rb_s[tid] = rel_bias[h * (2 * MREL - 1) + tid];
    const __half* Qg = qkv + (size_t)b * Ll * D3 + h * HD;
    const __half* Kg = Qg + Dd;
    #pragma unroll
    for (int i = 0; i < 4; i++) {
        int t = tid + i * 256;
        int r = t >> 3, s = t & 7;
        *(uint4*)&Qs[r][s * 8] = *(const uint4*)(Qg + (size_t)(q0 + r) * D3 + s * 8);
        *(uint4*)&Ks[r][s * 8] = *(const uint4*)(Kg + (size_t)(k0 + r) * D3 + s * 8);
    }
    __syncthreads();
    int wm0 = (wid >> 1) * 32, wn0 = (wid & 1) * 64;
    float acc[2][8][4] = {};
    #pragma unroll
    for (int ks = 0; ks < 64; ks += 16) {
        uint32_t a[2][4], bfr[8][2];
        #pragma unroll
        for (int i = 0; i < 2; i++)
            ldsm_x4(a[i][0], a[i][1], a[i][2], a[i][3],
                    sm32(&Qs[wm0 + i * 16 + (lane & 15)][ks + (lane >> 4) * 8]));
        #pragma unroll
        for (int jp = 0; jp < 4; jp++)
            ldsm_x4(bfr[jp * 2][0], bfr[jp * 2][1], bfr[jp * 2 + 1][0], bfr[jp * 2 + 1][1],
                    sm32(&Ks[wn0 + (jp * 2 + (lane >> 4)) * 8 + (lane & 7)]
                            [ks + ((lane >> 3) & 1) * 8]));
        #pragma unroll
        for (int i = 0; i < 2; i++)
            #pragma unroll
            for (int j = 0; j < 8; j++) mma16(acc[i][j], a[i], bfr[j]);
    }
    const float scale = 0.125f;
    float esum[4] = {0.f, 0.f, 0.f, 0.f};
    #pragma unroll
    for (int i = 0; i < 2; i++) {
        #pragma unroll
        for (int j = 0; j < 8; j++) {
            #pragma unroll
            for (int half_ = 0; half_ < 2; half_++) {
                int qq = q0 + wm0 + i * 16 + (lane >> 2) + half_ * 8;
                size_t row = ((size_t)bh * Ll + qq) * Ll;
                int kk = k0 + wn0 + j * 8 + (lane & 3) * 2;
                float s0 = acc[i][j][half_ * 2]     * scale + rb_s[clampq(qq - kk)     + MREL - 1];
                float s1 = acc[i][j][half_ * 2 + 1] * scale + rb_s[clampq(qq - kk - 1) + MREL - 1];
                *(__half2*)(s16 + row + kk) = __floats2half2_rn(s0, s1);
                esum[i * 2 + half_] += __expf(s0) + __expf(s1);
            }
        }
    }
    #pragma unroll
    for (int e = 0; e < 4; e++) {
        esum[e] += __shfl_xor_sync(0xffffffffu, esum[e], 1);
        esum[e] += __shfl_xor_sync(0xffffffffu, esum[e], 2);
    }
    if ((lane & 3) == 0) {
        #pragma unroll
        for (int i = 0; i < 2; i++)
            #pragma unroll
            for (int half_ = 0; half_ < 2; half_++)
                psum_s[wm0 + i * 16 + (lane >> 2) + half_ * 8][wid & 1] = esum[i * 2 + half_];
    }
    __syncthreads();
    if (tid < 128) {
        float s = psum_s[tid][0] + psum_s[tid][1];
        psum[((size_t)bh * Ll + q0 + tid) * KTILES + blockIdx.x] = s;
    }
}

// ---------------- rowsum reduce: inv[row] = 1 / sum_k psum[row][k] ----------------
__global__ void rsum_kernel(const float* __restrict__ psum, float* __restrict__ invs) {
    int row = blockIdx.x * 256 + threadIdx.x;
    const float4* p = (const float4*)(psum + (size_t)row * KTILES);
    float4 a = p[0], b = p[1], c = p[2], d = p[3];
    float s = (a.x + a.y + a.z + a.w) + (b.x + b.y + b.z + b.w)
            + (c.x + c.y + c.z + c.w) + (d.x + d.y + d.z + d.w);
    invs[row] = 1.0f / s;
}

// ---------------- AV fused with prob-emission ----------------
// Block: 128q x 64d per (b,h). Reads fp16 scores, computes p = exp(s)*inv,
// writes fp32 p to d_out, fp16 p to smem, then mma with V.
__global__ void av_fused_kernel(const __half* __restrict__ s16, const __half* __restrict__ qkv,
                                const float* __restrict__ invs, float* __restrict__ attnf,
                                __half* __restrict__ o16) {
    int bh = blockIdx.z, b = bh >> 3, h = bh & 7;
    int q0 = blockIdx.x * 128;
    __shared__ __half As[2][128][40];
    __shared__ __half Vs[2][32][72];
    __shared__ float inv_s[128];
    int tid = threadIdx.x, lane = tid & 31, wid = tid >> 5;
    int wm0 = wid * 16;
    float acc[8][4] = {};
    const __half* Ag = s16 + ((size_t)bh * Ll + q0) * Ll;
    const __half* Vg = qkv + (size_t)b * Ll * D3 + 2 * Dd + h * HD;
    if (tid < 128) inv_s[tid] = invs[(size_t)bh * Ll + q0 + tid];
    auto load = [&](int t0, int st) {
        #pragma unroll
        for (int i = 0; i < 2; i++) {
            int t = tid + i * 256;
            int r = t >> 2, s = t & 3;
            cp16(&As[st][r][s * 8], Ag + (size_t)r * Ll + t0 + s * 8);
        }
        {
            int r = tid >> 3, s = tid & 7;
            cp16(&Vs[st][r][s * 8], Vg + (size_t)(t0 + r) * D3 + s * 8);
        }
    };
    load(0, 0); cp_commit();
    constexpr int NIT = Ll / 32;
    int cr = tid >> 1, cbase = (tid & 1) * 16;
    for (int it = 0; it < NIT; it++) {
        int cur = it & 1;
        int t0 = it * 32;
        if (it + 1 < NIT) { load((it + 1) * 32, cur ^ 1); cp_commit(); cp_wait<1>(); }
        else cp_wait<0>();
        __syncthreads();
        // convert scores -> probs: fp32 to global, fp16 back to smem
        {
            float inv = inv_s[cr];
            float* arow = attnf + ((size_t)bh * Ll + q0 + cr) * Ll + t0 + cbase;
            #pragma unroll
            for (int k = 0; k < 16; k += 4) {
                __half2 h0 = *(__half2*)&As[cur][cr][cbase + k];
                __half2 h1 = *(__half2*)&As[cur][cr][cbase + k + 2];
                float2 f0 = __half22float2(h0), f1 = __half22float2(h1);
                float p0 = __expf(f0.x) * inv, p1 = __expf(f0.y) * inv;
                float p2 = __expf(f1.x) * inv, p3 = __expf(f1.y) * inv;
                *(float4*)(arow + k) = make_float4(p0, p1, p2, p3);
                *(__half2*)&As[cur][cr][cbase + k]     = __floats2half2_rn(p0, p1);
                *(__half2*)&As[cur][cr][cbase + k + 2] = __floats2half2_rn(p2, p3);
            }
        }
        __syncthreads();
        #pragma unroll
        for (int ks = 0; ks < 32; ks += 16) {
            uint32_t a[4], bfr[8][2];
            ldsm_x4(a[0], a[1], a[2], a[3],
                    sm32(&As[cur][wm0 + (lane & 15)][ks + (lane >> 4) * 8]));
            #pragma unroll
            for (int jp = 0; jp < 4; jp++)
                ldsm_x4t(bfr[jp * 2][0], bfr[jp * 2][1], bfr[jp * 2 + 1][0], bfr[jp * 2 + 1][1],
                         sm32(&Vs[cur][ks + (lane & 7) + ((lane >> 3) & 1) * 8]
                                 [(jp * 2 + (lane >> 4)) * 8]));
            #pragma unroll
            for (int j = 0; j < 8; j++) mma16(acc[j], a, bfr[j]);
        }
        __syncthreads();
    }
    #pragma unroll
    for (int j = 0; j < 8; j++) {
        int q = q0 + wm0 + (lane >> 2);
        int c = j * 8 + (lane & 3) * 2;
        __half* dst = o16 + (size_t)(b * Ll + q) * Dd + h * HD + c;
        *(__half2*)dst = __floats2half2_rn(acc[j][0], acc[j][1]);
        *(__half2*)(dst + (size_t)8 * Dd) = __floats2half2_rn(acc[j][2], acc[j][3]);
    }
}

// ---------------- FFN-in GEMM + fused GEGLU, cp.async double-buffered ----------------
__global__ void gemm_geglu_kernel(const __half* __restrict__ A, const __half* __restrict__ W,
                                  const float* __restrict__ bias, __half* __restrict__ F) {
    __shared__ __half As[2][128][40];
    __shared__ __half Bs[2][2][32][72];
    int bm = blockIdx.y * 128, bn = blockIdx.x * 64;
    int tid = threadIdx.x, lane = tid & 31, wid = tid >> 5;
    int wm = (wid >> 1) * 32, wn = (wid & 1) * 32;
    float acc[2][2][4][4] = {};
    auto load = [&](int k0, int st) {
        #pragma unroll
        for (int i = 0; i < 2; i++) {
            int t = tid + i * 256;
            int r = t >> 2, s = t & 3;
            cp16(&As[st][r][s * 8], A + (size_t)(bm + r) * Dd + k0 + s * 8);
        }
        {
            int r = tid >> 3, s = tid & 7;
            #pragma unroll
            for (int hh = 0; hh < 2; hh++)
                cp16(&Bs[st][hh][r][s * 8],
                     W + (size_t)(k0 + r) * (2 * DH) + bn + hh * DH + s * 8);
        }
    };
    load(0, 0); cp_commit();
    constexpr int NIT = Dd / 32;
    for (int it = 0; it < NIT; it++) {
        int cur = it & 1;
        if (it + 1 < NIT) { load((it + 1) * 32, cur ^ 1); cp_commit(); cp_wait<1>(); }
        else cp_wait<0>();
        __syncthreads();
        #pragma unroll
        for (int ks = 0; ks < 32; ks += 16) {
            uint32_t a[2][4];
            #pragma unroll
            for (int mi = 0; mi < 2; mi++)
                ldsm_x4(a[mi][0], a[mi][1], a[mi][2], a[mi][3],
                        sm32(&As[cur][wm + mi * 16 + (lane & 15)][ks + (lane >> 4) * 8]));
            #pragma unroll
            for (int hh = 0; hh < 2; hh++)
                #pragma unroll
                for (int nj = 0; nj < 4; nj++) {
                    uint32_t bfr[2];
                    ldsm_x2t(bfr[0], bfr[1], sm32(&Bs[cur][hh][ks + (lane & 15)][wn + nj * 8]));
                    #pragma unroll
                    for (int mi = 0; mi < 2; mi++) mma16(acc[hh][mi][nj], a[mi], bfr);
                }
        }
        __syncthreads();
    }
    #pragma unroll
    for (int mi = 0; mi < 2; mi++) {
        #pragma unroll
        for (int nj = 0; nj < 4; nj++) {
            int r = bm + wm + mi * 16 + (lane >> 2);
            int c = bn + wn + nj * 8 + (lane & 3) * 2;
            float ba0 = bias[c], ba1 = bias[c + 1];
            float bb0 = bias[c + DH], bb1 = bias[c + DH + 1];
            #pragma unroll
            for (int hh = 0; hh < 2; hh++) {
                float av0 = acc[0][mi][nj][hh * 2]     + ba0;
                float av1 = acc[0][mi][nj][hh * 2 + 1] + ba1;
                float bg0 = acc[1][mi][nj][hh * 2]     + bb0;
                float bg1 = acc[1][mi][nj][hh * 2 + 1] + bb1;
                float g0 = 0.5f * bg0 * (1.0f + erff(bg0 * 0.70710678118654752f));
                float g1 = 0.5f * bg1 * (1.0f + erff(bg1 * 0.70710678118654752f));
                size_t idx = (size_t)(r + hh * 8) * DH + c;
                *(__half2*)(F + idx) = __floats2half2_rn(g0 * av0, g1 * av1);
            }
        }
    }
}

extern "C" void kernel_launch(void* const* d_in, const int* in_sizes, int n_in,
                              void* d_out, int out_size) {
    const float* x        = (const float*)d_in[0];
    const float* ln1_w    = (const float*)d_in[1];
    const float* ln1_b    = (const float*)d_in[2];
    const float* qkv_w    = (const float*)d_in[3];
    const float* qkv_b    = (const float*)d_in[4];
    const float* out_w    = (const float*)d_in[5];
    const float* out_b    = (const float*)d_in[6];
    const float* rel_bias = (const float*)d_in[7];
    const float* gamma1   = (const float*)d_in[8];
    const float* ln2_w    = (const float*)d_in[9];
    const float* ln2_b    = (const float*)d_in[10];
    const float* ffn_in_w = (const float*)d_in[11];
    const float* ffn_in_b = (const float*)d_in[12];
    const float* ffn_out_w= (const float*)d_in[13];
    const float* ffn_out_b= (const float*)d_in[14];
    const float* gamma2   = (const float*)d_in[15];

    float* out_x = (float*)d_out;
    float* attn  = (float*)d_out + XSIZE;

    __half *h16, *qkv16, *o16, *f16, *attn16, *w16;
    float *x1, *psum, *invs;
    cudaGetSymbolAddress((void**)&h16,    g_h16);
    cudaGetSymbolAddress((void**)&qkv16,  g_qkv16);
    cudaGetSymbolAddress((void**)&o16,    g_o16);
    cudaGetSymbolAddress((void**)&f16,    g_f16);
    cudaGetSymbolAddress((void**)&attn16, g_attn16);
    cudaGetSymbolAddress((void**)&w16,    g_w16);
    cudaGetSymbolAddress((void**)&x1,     g_x1);
    cudaGetSymbolAddress((void**)&psum,   g_psum);
    cudaGetSymbolAddress((void**)&invs,   g_inv);

    // 0. convert all weights to fp16 in one launch
    f2h_all_kernel<<<(int)(E3 / 256), 256>>>((const float4*)qkv_w, (const float4*)out_w,
                                             (const float4*)ffn_in_w, (const float4*)ffn_out_w,
                                             (__half2*)w16);
    // 1. h16 = LN1(x)
    ln_kernel<<<BL, 256>>>(x, ln1_w, ln1_b, h16);
    // 2. qkv16 = h16 @ qkv_w + qkv_b
    gemm16_kernel<0><<<dim3(D3 / 128, BL / 128), 256>>>(h16, w16 + OFF_QKVW, qkv_b, qkv16, nullptr, nullptr, nullptr, D3, Dd);
    // 3. fp16 scores + per-tile partial expsums
    score16_kernel<<<dim3(KTILES, Ll / 128, Bb * Hh), 256>>>(qkv16, rel_bias, attn16, psum);
    // 4. rowsum reduce -> inverse
    rsum_kernel<<<NROWS / 256, 256>>>(psum, invs);
    // 5. fused: probs (fp32 -> d_out) + o16 = P @ V
    av_fused_kernel<<<dim3(Ll / 128, 1, Bb * Hh), 256>>>(attn16, qkv16, invs, attn, o16);
    // 6. x1 = x + (o16 @ out_w + out_b) * gamma1
    gemm16_kernel<1><<<dim3(Dd / 128, BL / 128), 256>>>(o16, w16 + OFF_OUTW, out_b, nullptr, x1, x, gamma1, Dd, Dd);
    // 7. h16 = LN2(x1)
    ln_kernel<<<BL, 256>>>(x1, ln2_w, ln2_b, h16);
    // 8. f16 = geglu(h16 @ ffn_in_w + b)
    gemm_geglu_kernel<<<dim3(DH / 64, BL / 128), 256>>>(h16, w16 + OFF_FFNIN, ffn_in_b, f16);
    // 9. out_x = x1 + (f16 @ ffn_out_w + b) * gamma2
    gemm16_kernel<1><<<dim3(Dd / 128, BL / 128), 256>>>(f16, w16 + OFF_FFNOUT, ffn_out_b, nullptr, out_x, x1, gamma2, Dd, DH);
}

// round 6
// speedup vs baseline: 1.5829x; 1.0056x over previous
#include <cuda_runtime.h>
#include <cuda_fp16.h>
#include <math.h>
#include <stdint.h>

// Problem constants
constexpr int Bb  = 2;
constexpr int Ll  = 2048;
constexpr int Dd  = 512;
constexpr int Hh  = 8;
constexpr int HD  = 64;
constexpr int DH  = 2048;
constexpr int MREL = 128;
constexpr int D3  = 3 * Dd;    // 1536
constexpr int BL  = Bb * Ll;   // 4096
constexpr long long XSIZE  = (long long)BL * Dd;
constexpr long long ATTN_N = (long long)Bb * Hh * Ll * Ll;  // 67,108,864
constexpr int NROWS = Bb * Hh * Ll;        // 32768 attention rows
constexpr int KTILES = Ll / 128;           // 16

// fp16 staging buffers
__device__ __half g_h16  [BL * Dd];
__device__ __half g_qkv16[BL * D3];
__device__ __half g_o16  [BL * Dd];
__device__ __half g_f16  [BL * DH];
__device__ __half g_attn16[ATTN_N];   // fp16 unnormalized exp(score)
// fp16 weights: qkv_w | out_w | ffn_in_w | ffn_out_w  (contiguous)
constexpr long long OFF_QKVW   = 0;
constexpr long long OFF_OUTW   = OFF_QKVW  + (long long)Dd * D3;
constexpr long long OFF_FFNIN  = OFF_OUTW  + (long long)Dd * Dd;
constexpr long long OFF_FFNOUT = OFF_FFNIN + (long long)Dd * 2 * DH;
constexpr long long W16_TOTAL  = OFF_FFNOUT + (long long)DH * Dd;   // 4,194,304
__device__ __half g_w16[W16_TOTAL];
__device__ float  g_x1  [BL * Dd];
__device__ float  g_psum[(long long)NROWS * KTILES];  // per-(row, ktile) partial expsum
__device__ float  g_inv [NROWS];                      // 1/rowsum

// ---------------- helpers ----------------
static __device__ __forceinline__ uint32_t sm32(const void* p) {
    return (uint32_t)__cvta_generic_to_shared(p);
}
static __device__ __forceinline__ void cp16(void* dst, const void* src) {
    asm volatile("cp.async.cg.shared.global [%0], [%1], 16;\n"
                 :: "r"(sm32(dst)), "l"(__cvta_generic_to_global(src)));
}
static __device__ __forceinline__ void cp_commit() {
    asm volatile("cp.async.commit_group;\n");
}
template <int N> static __device__ __forceinline__ void cp_wait() {
    asm volatile("cp.async.wait_group %0;\n" :: "n"(N));
}
static __device__ __forceinline__ void ldsm_x4(uint32_t& r0, uint32_t& r1, uint32_t& r2, uint32_t& r3, uint32_t a) {
    asm volatile("ldmatrix.sync.aligned.m8n8.x4.shared.b16 {%0,%1,%2,%3}, [%4];\n"
                 : "=r"(r0), "=r"(r1), "=r"(r2), "=r"(r3) : "r"(a));
}
static __device__ __forceinline__ void ldsm_x4t(uint32_t& r0, uint32_t& r1, uint32_t& r2, uint32_t& r3, uint32_t a) {
    asm volatile("ldmatrix.sync.aligned.m8n8.x4.trans.shared.b16 {%0,%1,%2,%3}, [%4];\n"
                 : "=r"(r0), "=r"(r1), "=r"(r2), "=r"(r3) : "r"(a));
}
static __device__ __forceinline__ void ldsm_x2t(uint32_t& r0, uint32_t& r1, uint32_t a) {
    asm volatile("ldmatrix.sync.aligned.m8n8.x2.trans.shared.b16 {%0,%1}, [%2];\n"
                 : "=r"(r0), "=r"(r1) : "r"(a));
}
static __device__ __forceinline__ void mma16(float* c, const uint32_t* a, const uint32_t* b) {
    asm volatile("mma.sync.aligned.m16n8k16.row.col.f32.f16.f16.f32 "
                 "{%0,%1,%2,%3}, {%4,%5,%6,%7}, {%8,%9}, {%0,%1,%2,%3};\n"
                 : "+f"(c[0]), "+f"(c[1]), "+f"(c[2]), "+f"(c[3])
                 : "r"(a[0]), "r"(a[1]), "r"(a[2]), "r"(a[3]), "r"(b[0]), "r"(b[1]));
}
static __device__ __forceinline__ int clampq(int d) {
    return d < -(MREL - 1) ? -(MREL - 1) : (d > (MREL - 1) ? (MREL - 1) : d);
}

// ---------------- all weights fp32 -> fp16, one launch ----------------
constexpr long long E0 = OFF_OUTW   / 4;
constexpr long long E1 = OFF_FFNIN  / 4;
constexpr long long E2 = OFF_FFNOUT / 4;
constexpr long long E3 = W16_TOTAL  / 4;
__global__ void f2h_all_kernel(const float4* __restrict__ a, const float4* __restrict__ b,
                               const float4* __restrict__ c, const float4* __restrict__ d,
                               __half2* __restrict__ dst) {
    long long i = (long long)blockIdx.x * 256 + threadIdx.x;
    const float4* src; long long off;
    if (i < E0)      { src = a; off = 0;  }
    else if (i < E1) { src = b; off = E0; }
    else if (i < E2) { src = c; off = E1; }
    else             { src = d; off = E2; }
    float4 v = src[i - off];
    dst[i * 2]     = __floats2half2_rn(v.x, v.y);
    dst[i * 2 + 1] = __floats2half2_rn(v.z, v.w);
}

// ---------------- LayerNorm -> fp16 out ----------------
__global__ void ln_kernel(const float* __restrict__ x, const float* __restrict__ w,
                          const float* __restrict__ b, __half* __restrict__ out) {
    int row = blockIdx.x;
    const float* xr = x + (long long)row * Dd;
    int t = threadIdx.x; // 256
    float v0 = xr[t], v1 = xr[t + 256];
    __shared__ float red[256];
    red[t] = v0 + v1;
    __syncthreads();
    #pragma unroll
    for (int o = 128; o > 0; o >>= 1) { if (t < o) red[t] += red[t + o]; __syncthreads(); }
    float mu = red[0] * (1.0f / Dd);
    __syncthreads();
    float d0 = v0 - mu, d1 = v1 - mu;
    red[t] = d0 * d0 + d1 * d1;
    __syncthreads();
    #pragma unroll
    for (int o = 128; o > 0; o >>= 1) { if (t < o) red[t] += red[t + o]; __syncthreads(); }
    float rstd = rsqrtf(red[0] * (1.0f / Dd) + 1e-5f);
    __half* orow = out + (long long)row * Dd;
    orow[t]       = __float2half(d0 * rstd * w[t]       + b[t]);
    orow[t + 256] = __float2half(d1 * rstd * w[t + 256] + b[t + 256]);
}

// ---------------- Tensor-core GEMM, cp.async double-buffered ----------------
// MODE 0: half out = acc+bias.  MODE 1: float out = resid + (acc+bias)*gamma.
template <int MODE>
__global__ void gemm16_kernel(const __half* __restrict__ A, const __half* __restrict__ W,
                              const float* __restrict__ bias, __half* __restrict__ Ch,
                              float* __restrict__ Cf, const float* __restrict__ resid,
                              const float* __restrict__ gamma, int N, int K) {
    __shared__ __half As[2][128][40];
    __shared__ __half Bs[2][32][136];
    int bm = blockIdx.y * 128, bn = blockIdx.x * 128;
    int tid = threadIdx.x, lane = tid & 31, wid = tid >> 5;
    int wm0 = (wid & 1) * 64, wn0 = (wid >> 1) * 32;

    auto load = [&](int k0, int st) {
        #pragma unroll
        for (int i = 0; i < 2; i++) {
            int t = tid + i * 256;
            int r = t >> 2, s = t & 3;
            cp16(&As[st][r][s * 8], A + (size_t)(bm + r) * K + k0 + s * 8);
        }
        #pragma unroll
        for (int i = 0; i < 2; i++) {
            int t = tid + i * 256;
            int r = t >> 4, s = t & 15;
            cp16(&Bs[st][r][s * 8], W + (size_t)(k0 + r) * N + bn + s * 8);
        }
    };
    load(0, 0); cp_commit();
    float acc[4][4][4] = {};
    int nIter = K / 32;
    for (int it = 0; it < nIter; it++) {
        int cur = it & 1;
        if (it + 1 < nIter) { load((it + 1) * 32, cur ^ 1); cp_commit(); cp_wait<1>(); }
        else cp_wait<0>();
        __syncthreads();
        #pragma unroll
        for (int ks = 0; ks < 32; ks += 16) {
            uint32_t a[4][4], b[4][2];
            #pragma unroll
            for (int i = 0; i < 4; i++)
                ldsm_x4(a[i][0], a[i][1], a[i][2], a[i][3],
                        sm32(&As[cur][wm0 + i * 16 + (lane & 15)][ks + (lane >> 4) * 8]));
            #pragma unroll
            for (int j = 0; j < 4; j++)
                ldsm_x2t(b[j][0], b[j][1], sm32(&Bs[cur][ks + (lane & 15)][wn0 + j * 8]));
            #pragma unroll
            for (int i = 0; i < 4; i++)
                #pragma unroll
                for (int j = 0; j < 4; j++) mma16(acc[i][j], a[i], b[j]);
        }
        __syncthreads();
    }
    #pragma unroll
    for (int i = 0; i < 4; i++) {
        #pragma unroll
        for (int j = 0; j < 4; j++) {
            int r = bm + wm0 + i * 16 + (lane >> 2);
            int c = bn + wn0 + j * 8 + (lane & 3) * 2;
            #pragma unroll
            for (int hh = 0; hh < 2; hh++) {
                size_t idx = (size_t)(r + hh * 8) * N + c;
                float v0 = acc[i][j][hh * 2]     + bias[c];
                float v1 = acc[i][j][hh * 2 + 1] + bias[c + 1];
                if (MODE == 0) {
                    *(__half2*)(Ch + idx) = __floats2half2_rn(v0, v1);
                } else {
                    float2 rv = *(const float2*)(resid + idx);
                    float2 ov = make_float2(rv.x + v0 * gamma[c], rv.y + v1 * gamma[c + 1]);
                    *(float2*)(Cf + idx) = ov;
                }
            }
        }
    }
}

// ---------------- Scores: e = exp(scale*(Q K^T) + rel_bias) -> fp16 + partial expsums --------
__global__ void score16_kernel(const __half* __restrict__ qkv, const float* __restrict__ rel_bias,
                               __half* __restrict__ e16, float* __restrict__ psum) {
    int bh = blockIdx.z, b = bh >> 3, h = bh & 7;
    int q0 = blockIdx.y * 128, k0 = blockIdx.x * 128;
    __shared__ __half Qs[128][72];
    __shared__ __half Ks[128][72];
    __shared__ float rb_s[2 * MREL - 1];
    __shared__ float psum_s[128][2];
    int tid = threadIdx.x, lane = tid & 31, wid = tid >> 5;
    if (tid < 2 * MREL - 1) rb_s[tid] = rel_bias[h * (2 * MREL - 1) + tid];
    const __half* Qg = qkv + (size_t)b * Ll * D3 + h * HD;
    const __half* Kg = Qg + Dd;
    #pragma unroll
    for (int i = 0; i < 4; i++) {
        int t = tid + i * 256;
        int r = t >> 3, s = t & 7;
        *(uint4*)&Qs[r][s * 8] = *(const uint4*)(Qg + (size_t)(q0 + r) * D3 + s * 8);
        *(uint4*)&Ks[r][s * 8] = *(const uint4*)(Kg + (size_t)(k0 + r) * D3 + s * 8);
    }
    __syncthreads();
    int wm0 = (wid >> 1) * 32, wn0 = (wid & 1) * 64;
    float acc[2][8][4] = {};
    #pragma unroll
    for (int ks = 0; ks < 64; ks += 16) {
        uint32_t a[2][4], bfr[8][2];
        #pragma unroll
        for (int i = 0; i < 2; i++)
            ldsm_x4(a[i][0], a[i][1], a[i][2], a[i][3],
                    sm32(&Qs[wm0 + i * 16 + (lane & 15)][ks + (lane >> 4) * 8]));
        #pragma unroll
        for (int jp = 0; jp < 4; jp++)
            ldsm_x4(bfr[jp * 2][0], bfr[jp * 2][1], bfr[jp * 2 + 1][0], bfr[jp * 2 + 1][1],
                    sm32(&Ks[wn0 + (jp * 2 + (lane >> 4)) * 8 + (lane & 7)]
                            [ks + ((lane >> 3) & 1) * 8]));
        #pragma unroll
        for (int i = 0; i < 2; i++)
            #pragma unroll
            for (int j = 0; j < 8; j++) mma16(acc[i][j], a[i], bfr[j]);
    }
    const float scale = 0.125f;
    float esum[4] = {0.f, 0.f, 0.f, 0.f};
    int dt = q0 - k0;
    bool cst = (dt >= 254) || (dt <= -254);
    float rbc = (dt >= 254) ? rb_s[2 * MREL - 2] : rb_s[0];

    auto epi = [&](auto getrb) {
        #pragma unroll
        for (int i = 0; i < 2; i++) {
            #pragma unroll
            for (int j = 0; j < 8; j++) {
                #pragma unroll
                for (int half_ = 0; half_ < 2; half_++) {
                    int qq = q0 + wm0 + i * 16 + (lane >> 2) + half_ * 8;
                    size_t row = ((size_t)bh * Ll + qq) * Ll;
                    int kk = k0 + wn0 + j * 8 + (lane & 3) * 2;
                    float s0 = acc[i][j][half_ * 2]     * scale + getrb(qq - kk);
                    float s1 = acc[i][j][half_ * 2 + 1] * scale + getrb(qq - kk - 1);
                    float e0 = __expf(s0), e1 = __expf(s1);
                    *(__half2*)(e16 + row + kk) = __floats2half2_rn(e0, e1);
                    esum[i * 2 + half_] += e0 + e1;
                }
            }
        }
    };
    if (cst) epi([&](int d) { return rbc; });
    else     epi([&](int d) { return rb_s[clampq(d) + MREL - 1]; });

    #pragma unroll
    for (int e = 0; e < 4; e++) {
        esum[e] += __shfl_xor_sync(0xffffffffu, esum[e], 1);
        esum[e] += __shfl_xor_sync(0xffffffffu, esum[e], 2);
    }
    if ((lane & 3) == 0) {
        #pragma unroll
        for (int i = 0; i < 2; i++)
            #pragma unroll
            for (int half_ = 0; half_ < 2; half_++)
                psum_s[wm0 + i * 16 + (lane >> 2) + half_ * 8][wid & 1] = esum[i * 2 + half_];
    }
    __syncthreads();
    if (tid < 128) {
        float s = psum_s[tid][0] + psum_s[tid][1];
        psum[((size_t)bh * Ll + q0 + tid) * KTILES + blockIdx.x] = s;
    }
}

// ---------------- rowsum reduce: inv[row] = 1 / sum_k psum[row][k] ----------------
__global__ void rsum_kernel(const float* __restrict__ psum, float* __restrict__ invs) {
    int row = blockIdx.x * 256 + threadIdx.x;
    const float4* p = (const float4*)(psum + (size_t)row * KTILES);
    float4 a = p[0], b = p[1], c = p[2], d = p[3];
    float s = (a.x + a.y + a.z + a.w) + (b.x + b.y + b.z + b.w)
            + (c.x + c.y + c.z + c.w) + (d.x + d.y + d.z + d.w);
    invs[row] = 1.0f / s;
}

// ---------------- AV fused: p32 emit (e*inv) + MMA on raw e16, final scale by inv ----------------
__global__ void av_fused_kernel(const __half* __restrict__ e16, const __half* __restrict__ qkv,
                                const float* __restrict__ invs, float* __restrict__ attnf,
                                __half* __restrict__ o16) {
    int bh = blockIdx.z, b = bh >> 3, h = bh & 7;
    int q0 = blockIdx.x * 128;
    __shared__ __half As[2][128][40];
    __shared__ __half Vs[2][32][72];
    __shared__ float inv_s[128];
    int tid = threadIdx.x, lane = tid & 31, wid = tid >> 5;
    int wm0 = wid * 16;
    float acc[8][4] = {};
    const __half* Ag = e16 + ((size_t)bh * Ll + q0) * Ll;
    const __half* Vg = qkv + (size_t)b * Ll * D3 + 2 * Dd + h * HD;
    if (tid < 128) inv_s[tid] = invs[(size_t)bh * Ll + q0 + tid];
    auto load = [&](int t0, int st) {
        #pragma unroll
        for (int i = 0; i < 2; i++) {
            int t = tid + i * 256;
            int r = t >> 2, s = t & 3;
            cp16(&As[st][r][s * 8], Ag + (size_t)r * Ll + t0 + s * 8);
        }
        {
            int r = tid >> 3, s = tid & 7;
            cp16(&Vs[st][r][s * 8], Vg + (size_t)(t0 + r) * D3 + s * 8);
        }
    };
    load(0, 0); cp_commit();
    constexpr int NIT = Ll / 32;
    int cr = tid >> 1, cbase = (tid & 1) * 16;
    float cinv = 0.f;   // set after inv_s is visible (post first sync)
    for (int it = 0; it < NIT; it++) {
        int cur = it & 1;
        int t0 = it * 32;
        if (it + 1 < NIT) { load((it + 1) * 32, cur ^ 1); cp_commit(); cp_wait<1>(); }
        else cp_wait<0>();
        __syncthreads();
        if (it == 0) cinv = inv_s[cr];
        // emit fp32 probs p = e * inv (no smem modification)
        {
            float* arow = attnf + ((size_t)bh * Ll + q0 + cr) * Ll + t0 + cbase;
            #pragma unroll
            for (int k = 0; k < 16; k += 4) {
                __half2 h0 = *(__half2*)&As[cur][cr][cbase + k];
                __half2 h1 = *(__half2*)&As[cur][cr][cbase + k + 2];
                float2 f0 = __half22float2(h0), f1 = __half22float2(h1);
                *(float4*)(arow + k) = make_float4(f0.x * cinv, f0.y * cinv,
                                                   f1.x * cinv, f1.y * cinv);
            }
        }
        #pragma unroll
        for (int ks = 0; ks < 32; ks += 16) {
            uint32_t a[4], bfr[8][2];
            ldsm_x4(a[0], a[1], a[2], a[3],
                    sm32(&As[cur][wm0 + (lane & 15)][ks + (lane >> 4) * 8]));
            #pragma unroll
            for (int jp = 0; jp < 4; jp++)
                ldsm_x4t(bfr[jp * 2][0], bfr[jp * 2][1], bfr[jp * 2 + 1][0], bfr[jp * 2 + 1][1],
                         sm32(&Vs[cur][ks + (lane & 7) + ((lane >> 3) & 1) * 8]
                                 [(jp * 2 + (lane >> 4)) * 8]));
            #pragma unroll
            for (int j = 0; j < 8; j++) mma16(acc[j], a, bfr[j]);
        }
        __syncthreads();
    }
    float inv0 = inv_s[wm0 + (lane >> 2)];
    float inv1 = inv_s[wm0 + (lane >> 2) + 8];
    #pragma unroll
    for (int j = 0; j < 8; j++) {
        int q = q0 + wm0 + (lane >> 2);
        int c = j * 8 + (lane & 3) * 2;
        __half* dst = o16 + (size_t)(b * Ll + q) * Dd + h * HD + c;
        *(__half2*)dst = __floats2half2_rn(acc[j][0] * inv0, acc[j][1] * inv0);
        *(__half2*)(dst + (size_t)8 * Dd) = __floats2half2_rn(acc[j][2] * inv1, acc[j][3] * inv1);
    }
}

// ---------------- FFN-in GEMM + fused GEGLU, cp.async double-buffered ----------------
__global__ void gemm_geglu_kernel(const __half* __restrict__ A, const __half* __restrict__ W,
                                  const float* __restrict__ bias, __half* __restrict__ F) {
    __shared__ __half As[2][128][40];
    __shared__ __half Bs[2][2][32][72];
    int bm = blockIdx.y * 128, bn = blockIdx.x * 64;
    int tid = threadIdx.x, lane = tid & 31, wid = tid >> 5;
    int wm = (wid >> 1) * 32, wn = (wid & 1) * 32;
    float acc[2][2][4][4] = {};
    auto load = [&](int k0, int st) {
        #pragma unroll
        for (int i = 0; i < 2; i++) {
            int t = tid + i * 256;
            int r = t >> 2, s = t & 3;
            cp16(&As[st][r][s * 8], A + (size_t)(bm + r) * Dd + k0 + s * 8);
        }
        {
            int r = tid >> 3, s = tid & 7;
            #pragma unroll
            for (int hh = 0; hh < 2; hh++)
                cp16(&Bs[st][hh][r][s * 8],
                     W + (size_t)(k0 + r) * (2 * DH) + bn + hh * DH + s * 8);
        }
    };
    load(0, 0); cp_commit();
    constexpr int NIT = Dd / 32;
    for (int it = 0; it < NIT; it++) {
        int cur = it & 1;
        if (it + 1 < NIT) { load((it + 1) * 32, cur ^ 1); cp_commit(); cp_wait<1>(); }
        else cp_wait<0>();
        __syncthreads();
        #pragma unroll
        for (int ks = 0; ks < 32; ks += 16) {
            uint32_t a[2][4];
            #pragma unroll
            for (int mi = 0; mi < 2; mi++)
                ldsm_x4(a[mi][0], a[mi][1], a[mi][2], a[mi][3],
                        sm32(&As[cur][wm + mi * 16 + (lane & 15)][ks + (lane >> 4) * 8]));
            #pragma unroll
            for (int hh = 0; hh < 2; hh++)
                #pragma unroll
                for (int nj = 0; nj < 4; nj++) {
                    uint32_t bfr[2];
                    ldsm_x2t(bfr[0], bfr[1], sm32(&Bs[cur][hh][ks + (lane & 15)][wn + nj * 8]));
                    #pragma unroll
                    for (int mi = 0; mi < 2; mi++) mma16(acc[hh][mi][nj], a[mi], bfr);
                }
        }
        __syncthreads();
    }
    #pragma unroll
    for (int mi = 0; mi < 2; mi++) {
        #pragma unroll
        for (int nj = 0; nj < 4; nj++) {
            int r = bm + wm + mi * 16 + (lane >> 2);
            int c = bn + wn + nj * 8 + (lane & 3) * 2;
            float ba0 = bias[c], ba1 = bias[c + 1];
            float bb0 = bias[c + DH], bb1 = bias[c + DH + 1];
            #pragma unroll
            for (int hh = 0; hh < 2; hh++) {
                float av0 = acc[0][mi][nj][hh * 2]     + ba0;
                float av1 = acc[0][mi][nj][hh * 2 + 1] + ba1;
                float bg0 = acc[1][mi][nj][hh * 2]     + bb0;
                float bg1 = acc[1][mi][nj][hh * 2 + 1] + bb1;
                float g0 = 0.5f * bg0 * (1.0f + erff(bg0 * 0.70710678118654752f));
                float g1 = 0.5f * bg1 * (1.0f + erff(bg1 * 0.70710678118654752f));
                size_t idx = (size_t)(r + hh * 8) * DH + c;
                *(__half2*)(F + idx) = __floats2half2_rn(g0 * av0, g1 * av1);
            }
        }
    }
}

extern "C" void kernel_launch(void* const* d_in, const int* in_sizes, int n_in,
                              void* d_out, int out_size) {
    const float* x        = (const float*)d_in[0];
    const float* ln1_w    = (const float*)d_in[1];
    const float* ln1_b    = (const float*)d_in[2];
    const float* qkv_w    = (const float*)d_in[3];
    const float* qkv_b    = (const float*)d_in[4];
    const float* out_w    = (const float*)d_in[5];
    const float* out_b    = (const float*)d_in[6];
    const float* rel_bias = (const float*)d_in[7];
    const float* gamma1   = (const float*)d_in[8];
    const float* ln2_w    = (const float*)d_in[9];
    const float* ln2_b    = (const float*)d_in[10];
    const float* ffn_in_w = (const float*)d_in[11];
    const float* ffn_in_b = (const float*)d_in[12];
    const float* ffn_out_w= (const float*)d_in[13];
    const float* ffn_out_b= (const float*)d_in[14];
    const float* gamma2   = (const float*)d_in[15];

    float* out_x = (float*)d_out;
    float* attn  = (float*)d_out + XSIZE;

    __half *h16, *qkv16, *o16, *f16, *attn16, *w16;
    float *x1, *psum, *invs;
    cudaGetSymbolAddress((void**)&h16,    g_h16);
    cudaGetSymbolAddress((void**)&qkv16,  g_qkv16);
    cudaGetSymbolAddress((void**)&o16,    g_o16);
    cudaGetSymbolAddress((void**)&f16,    g_f16);
    cudaGetSymbolAddress((void**)&attn16, g_attn16);
    cudaGetSymbolAddress((void**)&w16,    g_w16);
    cudaGetSymbolAddress((void**)&x1,     g_x1);
    cudaGetSymbolAddress((void**)&psum,   g_psum);
    cudaGetSymbolAddress((void**)&invs,   g_inv);

    // 0. convert all weights to fp16 in one launch
    f2h_all_kernel<<<(int)(E3 / 256), 256>>>((const float4*)qkv_w, (const float4*)out_w,
                                             (const float4*)ffn_in_w, (const float4*)ffn_out_w,
                                             (__half2*)w16);
    // 1. h16 = LN1(x)
    ln_kernel<<<BL, 256>>>(x, ln1_w, ln1_b, h16);
    // 2. qkv16 = h16 @ qkv_w + qkv_b
    gemm16_kernel<0><<<dim3(D3 / 128, BL / 128), 256>>>(h16, w16 + OFF_QKVW, qkv_b, qkv16, nullptr, nullptr, nullptr, D3, Dd);
    // 3. e16 = exp(scores) + per-tile partial expsums
    score16_kernel<<<dim3(KTILES, Ll / 128, Bb * Hh), 256>>>(qkv16, rel_bias, attn16, psum);
    // 4. rowsum reduce -> inverse
    rsum_kernel<<<NROWS / 256, 256>>>(psum, invs);
    // 5. fused: p32 = e*inv -> d_out; o16 = (e @ V) * inv
    av_fused_kernel<<<dim3(Ll / 128, 1, Bb * Hh), 256>>>(attn16, qkv16, invs, attn, o16);
    // 6. x1 = x + (o16 @ out_w + out_b) * gamma1
    gemm16_kernel<1><<<dim3(Dd / 128, BL / 128), 256>>>(o16, w16 + OFF_OUTW, out_b, nullptr, x1, x, gamma1, Dd, Dd);
    // 7. h16 = LN2(x1)
    ln_kernel<<<BL, 256>>>(x1, ln2_w, ln2_b, h16);
    // 8. f16 = geglu(h16 @ ffn_in_w + b)
    gemm_geglu_kernel<<<dim3(DH / 64, BL / 128), 256>>>(h16, w16 + OFF_FFNIN, ffn_in_b, f16);
    // 9. out_x = x1 + (f16 @ ffn_out_w + b) * gamma2
    gemm16_kernel<1><<<dim3(Dd / 128, BL / 128), 256>>>(f16, w16 + OFF_FFNOUT, ffn_out_b, nullptr, out_x, x1, gamma2, Dd, DH);
}

// round 7
// speedup vs baseline: 1.6087x; 1.0163x over previous
#include <cuda_runtime.h>
#include <cuda_fp16.h>
#include <math.h>
#include <stdint.h>

// Problem constants
constexpr int Bb  = 2;
constexpr int Ll  = 2048;
constexpr int Dd  = 512;
constexpr int Hh  = 8;
constexpr int HD  = 64;
constexpr int DH  = 2048;
constexpr int MREL = 128;
constexpr int D3  = 3 * Dd;    // 1536
constexpr int BL  = Bb * Ll;   // 4096
constexpr long long XSIZE  = (long long)BL * Dd;
constexpr long long ATTN_N = (long long)Bb * Hh * Ll * Ll;  // 67,108,864

// fp16 staging buffers
__device__ __half g_h16  [BL * Dd];
__device__ __half g_qkv16[BL * D3];
__device__ __half g_o16  [BL * Dd];
__device__ __half g_f16  [BL * DH];
__device__ __half g_attn16[ATTN_N];   // fp16 unnormalized exp(score)
// fp16 weights: qkv_w | out_w | ffn_in_w | ffn_out_w  (contiguous)
constexpr long long OFF_QKVW   = 0;
constexpr long long OFF_OUTW   = OFF_QKVW  + (long long)Dd * D3;
constexpr long long OFF_FFNIN  = OFF_OUTW  + (long long)Dd * Dd;
constexpr long long OFF_FFNOUT = OFF_FFNIN + (long long)Dd * 2 * DH;
constexpr long long W16_TOTAL  = OFF_FFNOUT + (long long)DH * Dd;   // 4,194,304
__device__ __half g_w16[W16_TOTAL];
__device__ float  g_x1  [BL * Dd];

// ---------------- helpers ----------------
static __device__ __forceinline__ uint32_t sm32(const void* p) {
    return (uint32_t)__cvta_generic_to_shared(p);
}
static __device__ __forceinline__ void cp16(void* dst, const void* src) {
    asm volatile("cp.async.cg.shared.global [%0], [%1], 16;\n"
                 :: "r"(sm32(dst)), "l"(__cvta_generic_to_global(src)));
}
static __device__ __forceinline__ void cp_commit() {
    asm volatile("cp.async.commit_group;\n");
}
template <int N> static __device__ __forceinline__ void cp_wait() {
    asm volatile("cp.async.wait_group %0;\n" :: "n"(N));
}
static __device__ __forceinline__ void ldsm_x4(uint32_t& r0, uint32_t& r1, uint32_t& r2, uint32_t& r3, uint32_t a) {
    asm volatile("ldmatrix.sync.aligned.m8n8.x4.shared.b16 {%0,%1,%2,%3}, [%4];\n"
                 : "=r"(r0), "=r"(r1), "=r"(r2), "=r"(r3) : "r"(a));
}
static __device__ __forceinline__ void ldsm_x4t(uint32_t& r0, uint32_t& r1, uint32_t& r2, uint32_t& r3, uint32_t a) {
    asm volatile("ldmatrix.sync.aligned.m8n8.x4.trans.shared.b16 {%0,%1,%2,%3}, [%4];\n"
                 : "=r"(r0), "=r"(r1), "=r"(r2), "=r"(r3) : "r"(a));
}
static __device__ __forceinline__ void ldsm_x2t(uint32_t& r0, uint32_t& r1, uint32_t a) {
    asm volatile("ldmatrix.sync.aligned.m8n8.x2.trans.shared.b16 {%0,%1}, [%2];\n"
                 : "=r"(r0), "=r"(r1) : "r"(a));
}
static __device__ __forceinline__ void mma16(float* c, const uint32_t* a, const uint32_t* b) {
    asm volatile("mma.sync.aligned.m16n8k16.row.col.f32.f16.f16.f32 "
                 "{%0,%1,%2,%3}, {%4,%5,%6,%7}, {%8,%9}, {%0,%1,%2,%3};\n"
                 : "+f"(c[0]), "+f"(c[1]), "+f"(c[2]), "+f"(c[3])
                 : "r"(a[0]), "r"(a[1]), "r"(a[2]), "r"(a[3]), "r"(b[0]), "r"(b[1]));
}
static __device__ __forceinline__ int clampq(int d) {
    return d < -(MREL - 1) ? -(MREL - 1) : (d > (MREL - 1) ? (MREL - 1) : d);
}

// ---------------- all weights fp32 -> fp16, one launch ----------------
constexpr long long E0 = OFF_OUTW   / 4;
constexpr long long E1 = OFF_FFNIN  / 4;
constexpr long long E2 = OFF_FFNOUT / 4;
constexpr long long E3 = W16_TOTAL  / 4;
__global__ void f2h_all_kernel(const float4* __restrict__ a, const float4* __restrict__ b,
                               const float4* __restrict__ c, const float4* __restrict__ d,
                               __half2* __restrict__ dst) {
    long long i = (long long)blockIdx.x * 256 + threadIdx.x;
    const float4* src; long long off;
    if (i < E0)      { src = a; off = 0;  }
    else if (i < E1) { src = b; off = E0; }
    else if (i < E2) { src = c; off = E1; }
    else             { src = d; off = E2; }
    float4 v = src[i - off];
    dst[i * 2]     = __floats2half2_rn(v.x, v.y);
    dst[i * 2 + 1] = __floats2half2_rn(v.z, v.w);
}

// ---------------- LayerNorm -> fp16 out ----------------
__global__ void ln_kernel(const float* __restrict__ x, const float* __restrict__ w,
                          const float* __restrict__ b, __half* __restrict__ out) {
    int row = blockIdx.x;
    const float* xr = x + (long long)row * Dd;
    int t = threadIdx.x; // 256
    float v0 = xr[t], v1 = xr[t + 256];
    __shared__ float red[256];
    red[t] = v0 + v1;
    __syncthreads();
    #pragma unroll
    for (int o = 128; o > 0; o >>= 1) { if (t < o) red[t] += red[t + o]; __syncthreads(); }
    float mu = red[0] * (1.0f / Dd);
    __syncthreads();
    float d0 = v0 - mu, d1 = v1 - mu;
    red[t] = d0 * d0 + d1 * d1;
    __syncthreads();
    #pragma unroll
    for (int o = 128; o > 0; o >>= 1) { if (t < o) red[t] += red[t + o]; __syncthreads(); }
    float rstd = rsqrtf(red[0] * (1.0f / Dd) + 1e-5f);
    __half* orow = out + (long long)row * Dd;
    orow[t]       = __float2half(d0 * rstd * w[t]       + b[t]);
    orow[t + 256] = __float2half(d1 * rstd * w[t + 256] + b[t + 256]);
}

// ---------------- Tensor-core GEMM, cp.async double-buffered ----------------
// MODE 0: half out = acc+bias.  MODE 1: float out = resid + (acc+bias)*gamma.
template <int MODE>
__global__ void gemm16_kernel(const __half* __restrict__ A, const __half* __restrict__ W,
                              const float* __restrict__ bias, __half* __restrict__ Ch,
                              float* __restrict__ Cf, const float* __restrict__ resid,
                              const float* __restrict__ gamma, int N, int K) {
    __shared__ __half As[2][128][40];
    __shared__ __half Bs[2][32][136];
    int bm = blockIdx.y * 128, bn = blockIdx.x * 128;
    int tid = threadIdx.x, lane = tid & 31, wid = tid >> 5;
    int wm0 = (wid & 1) * 64, wn0 = (wid >> 1) * 32;

    auto load = [&](int k0, int st) {
        #pragma unroll
        for (int i = 0; i < 2; i++) {
            int t = tid + i * 256;
            int r = t >> 2, s = t & 3;
            cp16(&As[st][r][s * 8], A + (size_t)(bm + r) * K + k0 + s * 8);
        }
        #pragma unroll
        for (int i = 0; i < 2; i++) {
            int t = tid + i * 256;
            int r = t >> 4, s = t & 15;
            cp16(&Bs[st][r][s * 8], W + (size_t)(k0 + r) * N + bn + s * 8);
        }
    };
    load(0, 0); cp_commit();
    float acc[4][4][4] = {};
    int nIter = K / 32;
    for (int it = 0; it < nIter; it++) {
        int cur = it & 1;
        if (it + 1 < nIter) { load((it + 1) * 32, cur ^ 1); cp_commit(); cp_wait<1>(); }
        else cp_wait<0>();
        __syncthreads();
        #pragma unroll
        for (int ks = 0; ks < 32; ks += 16) {
            uint32_t a[4][4], b[4][2];
            #pragma unroll
            for (int i = 0; i < 4; i++)
                ldsm_x4(a[i][0], a[i][1], a[i][2], a[i][3],
                        sm32(&As[cur][wm0 + i * 16 + (lane & 15)][ks + (lane >> 4) * 8]));
            #pragma unroll
            for (int j = 0; j < 4; j++)
                ldsm_x2t(b[j][0], b[j][1], sm32(&Bs[cur][ks + (lane & 15)][wn0 + j * 8]));
            #pragma unroll
            for (int i = 0; i < 4; i++)
                #pragma unroll
                for (int j = 0; j < 4; j++) mma16(acc[i][j], a[i], b[j]);
        }
        __syncthreads();
    }
    #pragma unroll
    for (int i = 0; i < 4; i++) {
        #pragma unroll
        for (int j = 0; j < 4; j++) {
            int r = bm + wm0 + i * 16 + (lane >> 2);
            int c = bn + wn0 + j * 8 + (lane & 3) * 2;
            #pragma unroll
            for (int hh = 0; hh < 2; hh++) {
                size_t idx = (size_t)(r + hh * 8) * N + c;
                float v0 = acc[i][j][hh * 2]     + bias[c];
                float v1 = acc[i][j][hh * 2 + 1] + bias[c + 1];
                if (MODE == 0) {
                    *(__half2*)(Ch + idx) = __floats2half2_rn(v0, v1);
                } else {
                    float2 rv = *(const float2*)(resid + idx);
                    float2 ov = make_float2(rv.x + v0 * gamma[c], rv.y + v1 * gamma[c + 1]);
                    *(float2*)(Cf + idx) = ov;
                }
            }
        }
    }
}

// ---------------- Fused attention: scores+exp+rowsum+probs+AV in one kernel ----------------
// Grid: (q-tiles=16, bh=16). One wave (256 CTAs). Dynamic smem:
//   [0)       Qs     128x72 half        = 18432 B
//   [18432)   buf0   (K tile | A+V)     = 18432 B
//   [36864)   buf1                      = 18432 B
//   [55296)   psum_s 128x2 float        = 1024 B
//   [56320)   inv_s  128 float          = 512 B   (total 56832)
__global__ void __launch_bounds__(256, 2)
attn_fused_kernel(const __half* __restrict__ qkv, const float* __restrict__ rel_bias,
                  __half* __restrict__ e16, float* __restrict__ attnf,
                  __half* __restrict__ o16) {
    extern __shared__ __align__(16) char dsm[];
    __half* Qs = (__half*)dsm;
    __half* bufs[2] = { (__half*)(dsm + 18432), (__half*)(dsm + 36864) };
    float* psum_s = (float*)(dsm + 55296);   // [128][2]
    float* inv_s  = (float*)(dsm + 56320);   // [128]
    __shared__ float rb_s[2 * MREL - 1];

    int bh = blockIdx.y, b = bh >> 3, h = bh & 7;
    int q0 = blockIdx.x * 128;
    int tid = threadIdx.x, lane = tid & 31, wid = tid >> 5;
    if (tid < 2 * MREL - 1) rb_s[tid] = rel_bias[h * (2 * MREL - 1) + tid];

    const __half* Qg = qkv + (size_t)b * Ll * D3 + h * HD;
    const __half* Kg = Qg + Dd;
    const __half* Vg = Qg + 2 * Dd;
    __half* Eg = e16 + ((size_t)bh * Ll + q0) * Ll;

    // load Q once (plain vector loads)
    #pragma unroll
    for (int i = 0; i < 4; i++) {
        int t = tid + i * 256;
        int r = t >> 3, s = t & 7;
        *(uint4*)(Qs + r * 72 + s * 8) = *(const uint4*)(Qg + (size_t)(q0 + r) * D3 + s * 8);
    }

    // ---- Phase A: e = exp(scores), row sums ----
    auto loadK = [&](int kt, __half* buf) {
        const __half* base = Kg + (size_t)(kt * 128) * D3;
        #pragma unroll
        for (int i = 0; i < 4; i++) {
            int t = tid + i * 256;
            int r = t >> 3, s = t & 7;
            cp16(buf + r * 72 + s * 8, base + (size_t)r * D3 + s * 8);
        }
    };
    loadK(0, bufs[0]); cp_commit();

    int wm0 = (wid >> 1) * 32, wn0 = (wid & 1) * 64;
    const float scale = 0.125f;
    float esum[4] = {0.f, 0.f, 0.f, 0.f};

    for (int kt = 0; kt < 16; kt++) {
        __half* cur = bufs[kt & 1];
        if (kt + 1 < 16) { loadK(kt + 1, bufs[(kt + 1) & 1]); cp_commit(); cp_wait<1>(); }
        else cp_wait<0>();
        __syncthreads();
        float acc[2][8][4] = {};
        #pragma unroll
        for (int ks = 0; ks < 64; ks += 16) {
            uint32_t a[2][4], bfr[8][2];
            #pragma unroll
            for (int i = 0; i < 2; i++)
                ldsm_x4(a[i][0], a[i][1], a[i][2], a[i][3],
                        sm32(Qs + (wm0 + i * 16 + (lane & 15)) * 72 + ks + (lane >> 4) * 8));
            #pragma unroll
            for (int jp = 0; jp < 4; jp++)
                ldsm_x4(bfr[jp * 2][0], bfr[jp * 2][1], bfr[jp * 2 + 1][0], bfr[jp * 2 + 1][1],
                        sm32(cur + (wn0 + (jp * 2 + (lane >> 4)) * 8 + (lane & 7)) * 72
                             + ks + ((lane >> 3) & 1) * 8));
            #pragma unroll
            for (int i = 0; i < 2; i++)
                #pragma unroll
                for (int j = 0; j < 8; j++) mma16(acc[i][j], a[i], bfr[j]);
        }
        int k0 = kt * 128;
        int dt = q0 - k0;
        bool cst = (dt >= 254) || (dt <= -254);
        float rbc = (dt >= 254) ? rb_s[2 * MREL - 2] : rb_s[0];
        #pragma unroll
        for (int i = 0; i < 2; i++) {
            #pragma unroll
            for (int j = 0; j < 8; j++) {
                #pragma unroll
                for (int half_ = 0; half_ < 2; half_++) {
                    int ql = wm0 + i * 16 + (lane >> 2) + half_ * 8;
                    int qq = q0 + ql;
                    int kk = k0 + wn0 + j * 8 + (lane & 3) * 2;
                    float rb0 = cst ? rbc : rb_s[clampq(qq - kk) + MREL - 1];
                    float rb1 = cst ? rbc : rb_s[clampq(qq - kk - 1) + MREL - 1];
                    float s0 = acc[i][j][half_ * 2]     * scale + rb0;
                    float s1 = acc[i][j][half_ * 2 + 1] * scale + rb1;
                    float e0 = __expf(s0), e1 = __expf(s1);
                    *(__half2*)(Eg + (size_t)ql * Ll + kk) = __floats2half2_rn(e0, e1);
                    esum[i * 2 + half_] += e0 + e1;
                }
            }
        }
        __syncthreads();
    }
    // block-wide row sums -> inv_s
    #pragma unroll
    for (int e = 0; e < 4; e++) {
        esum[e] += __shfl_xor_sync(0xffffffffu, esum[e], 1);
        esum[e] += __shfl_xor_sync(0xffffffffu, esum[e], 2);
    }
    if ((lane & 3) == 0) {
        #pragma unroll
        for (int i = 0; i < 2; i++)
            #pragma unroll
            for (int half_ = 0; half_ < 2; half_++)
                psum_s[(wm0 + i * 16 + (lane >> 2) + half_ * 8) * 2 + (wid & 1)] = esum[i * 2 + half_];
    }
    __syncthreads();
    if (tid < 128) inv_s[tid] = 1.0f / (psum_s[tid * 2] + psum_s[tid * 2 + 1]);
    __syncthreads();

    // ---- Phase B: p32 emit + o = (e @ V) * inv ----
    auto loadB = [&](int t0, __half* buf) {
        #pragma unroll
        for (int i = 0; i < 2; i++) {
            int t = tid + i * 256;
            int r = t >> 2, s = t & 3;
            cp16(buf + r * 40 + s * 8, Eg + (size_t)r * Ll + t0 + s * 8);
        }
        {
            int r = tid >> 3, s = tid & 7;
            cp16(buf + 5120 + r * 72 + s * 8, Vg + (size_t)(t0 + r) * D3 + s * 8);
        }
    };
    loadB(0, bufs[0]); cp_commit();
    float acc[8][4] = {};
    int awm = wid * 16;
    int cr = tid >> 1, cbase = (tid & 1) * 16;
    float cinv = inv_s[cr];
    constexpr int NIT = Ll / 32;
    for (int it = 0; it < NIT; it++) {
        __half* cur = bufs[it & 1];
        int t0 = it * 32;
        if (it + 1 < NIT) { loadB((it + 1) * 32, bufs[(it + 1) & 1]); cp_commit(); cp_wait<1>(); }
        else cp_wait<0>();
        __syncthreads();
        // emit fp32 probs p = e * inv
        {
            float* arow = attnf + ((size_t)bh * Ll + q0 + cr) * Ll + t0 + cbase;
            const __half* erow = cur + cr * 40 + cbase;
            #pragma unroll
            for (int k = 0; k < 16; k += 4) {
                __half2 h0 = *(__half2*)(erow + k);
                __half2 h1 = *(__half2*)(erow + k + 2);
                float2 f0 = __half22float2(h0), f1 = __half22float2(h1);
                *(float4*)(arow + k) = make_float4(f0.x * cinv, f0.y * cinv,
                                                   f1.x * cinv, f1.y * cinv);
            }
        }
        #pragma unroll
        for (int ks = 0; ks < 32; ks += 16) {
            uint32_t a[4], bfr[8][2];
            ldsm_x4(a[0], a[1], a[2], a[3],
                    sm32(cur + (awm + (lane & 15)) * 40 + ks + (lane >> 4) * 8));
            #pragma unroll
            for (int jp = 0; jp < 4; jp++)
                ldsm_x4t(bfr[jp * 2][0], bfr[jp * 2][1], bfr[jp * 2 + 1][0], bfr[jp * 2 + 1][1],
                         sm32(cur + 5120 + (ks + (lane & 7) + ((lane >> 3) & 1) * 8) * 72
                              + (jp * 2 + (lane >> 4)) * 8));
            #pragma unroll
            for (int j = 0; j < 8; j++) mma16(acc[j], a, bfr[j]);
        }
        __syncthreads();
    }
    float inv0 = inv_s[awm + (lane >> 2)];
    float inv1 = inv_s[awm + (lane >> 2) + 8];
    #pragma unroll
    for (int j = 0; j < 8; j++) {
        int q = q0 + awm + (lane >> 2);
        int c = j * 8 + (lane & 3) * 2;
        __half* dst = o16 + (size_t)(b * Ll + q) * Dd + h * HD + c;
        *(__half2*)dst = __floats2half2_rn(acc[j][0] * inv0, acc[j][1] * inv0);
        *(__half2*)(dst + (size_t)8 * Dd) = __floats2half2_rn(acc[j][2] * inv1, acc[j][3] * inv1);
    }
}

// ---------------- FFN-in GEMM + fused GEGLU, cp.async double-buffered ----------------
__global__ void gemm_geglu_kernel(const __half* __restrict__ A, const __half* __restrict__ W,
                                  const float* __restrict__ bias, __half* __restrict__ F) {
    __shared__ __half As[2][128][40];
    __shared__ __half Bs[2][2][32][72];
    int bm = blockIdx.y * 128, bn = blockIdx.x * 64;
    int tid = threadIdx.x, lane = tid & 31, wid = tid >> 5;
    int wm = (wid >> 1) * 32, wn = (wid & 1) * 32;
    float acc[2][2][4][4] = {};
    auto load = [&](int k0, int st) {
        #pragma unroll
        for (int i = 0; i < 2; i++) {
            int t = tid + i * 256;
            int r = t >> 2, s = t & 3;
            cp16(&As[st][r][s * 8], A + (size_t)(bm + r) * Dd + k0 + s * 8);
        }
        {
            int r = tid >> 3, s = tid & 7;
            #pragma unroll
            for (int hh = 0; hh < 2; hh++)
                cp16(&Bs[st][hh][r][s * 8],
                     W + (size_t)(k0 + r) * (2 * DH) + bn + hh * DH + s * 8);
        }
    };
    load(0, 0); cp_commit();
    constexpr int NIT = Dd / 32;
    for (int it = 0; it < NIT; it++) {
        int cur = it & 1;
        if (it + 1 < NIT) { load((it + 1) * 32, cur ^ 1); cp_commit(); cp_wait<1>(); }
        else cp_wait<0>();
        __syncthreads();
        #pragma unroll
        for (int ks = 0; ks < 32; ks += 16) {
            uint32_t a[2][4];
            #pragma unroll
            for (int mi = 0; mi < 2; mi++)
                ldsm_x4(a[mi][0], a[mi][1], a[mi][2], a[mi][3],
                        sm32(&As[cur][wm + mi * 16 + (lane & 15)][ks + (lane >> 4) * 8]));
            #pragma unroll
            for (int hh = 0; hh < 2; hh++)
                #pragma unroll
                for (int nj = 0; nj < 4; nj++) {
                    uint32_t bfr[2];
                    ldsm_x2t(bfr[0], bfr[1], sm32(&Bs[cur][hh][ks + (lane & 15)][wn + nj * 8]));
                    #pragma unroll
                    for (int mi = 0; mi < 2; mi++) mma16(acc[hh][mi][nj], a[mi], bfr);
                }
        }
        __syncthreads();
    }
    #pragma unroll
    for (int mi = 0; mi < 2; mi++) {
        #pragma unroll
        for (int nj = 0; nj < 4; nj++) {
            int r = bm + wm + mi * 16 + (lane >> 2);
            int c = bn + wn + nj * 8 + (lane & 3) * 2;
            float ba0 = bias[c], ba1 = bias[c + 1];
            float bb0 = bias[c + DH], bb1 = bias[c + DH + 1];
            #pragma unroll
            for (int hh = 0; hh < 2; hh++) {
                float av0 = acc[0][mi][nj][hh * 2]     + ba0;
                float av1 = acc[0][mi][nj][hh * 2 + 1] + ba1;
                float bg0 = acc[1][mi][nj][hh * 2]     + bb0;
                float bg1 = acc[1][mi][nj][hh * 2 + 1] + bb1;
                float g0 = 0.5f * bg0 * (1.0f + erff(bg0 * 0.70710678118654752f));
                float g1 = 0.5f * bg1 * (1.0f + erff(bg1 * 0.70710678118654752f));
                size_t idx = (size_t)(r + hh * 8) * DH + c;
                *(__half2*)(F + idx) = __floats2half2_rn(g0 * av0, g1 * av1);
            }
        }
    }
}

extern "C" void kernel_launch(void* const* d_in, const int* in_sizes, int n_in,
                              void* d_out, int out_size) {
    const float* x        = (const float*)d_in[0];
    const float* ln1_w    = (const float*)d_in[1];
    const float* ln1_b    = (const float*)d_in[2];
    const float* qkv_w    = (const float*)d_in[3];
    const float* qkv_b    = (const float*)d_in[4];
    const float* out_w    = (const float*)d_in[5];
    const float* out_b    = (const float*)d_in[6];
    const float* rel_bias = (const float*)d_in[7];
    const float* gamma1   = (const float*)d_in[8];
    const float* ln2_w    = (const float*)d_in[9];
    const float* ln2_b    = (const float*)d_in[10];
    const float* ffn_in_w = (const float*)d_in[11];
    const float* ffn_in_b = (const float*)d_in[12];
    const float* ffn_out_w= (const float*)d_in[13];
    const float* ffn_out_b= (const float*)d_in[14];
    const float* gamma2   = (const float*)d_in[15];

    float* out_x = (float*)d_out;
    float* attn  = (float*)d_out + XSIZE;

    __half *h16, *qkv16, *o16, *f16, *attn16, *w16;
    float *x1;
    cudaGetSymbolAddress((void**)&h16,    g_h16);
    cudaGetSymbolAddress((void**)&qkv16,  g_qkv16);
    cudaGetSymbolAddress((void**)&o16,    g_o16);
    cudaGetSymbolAddress((void**)&f16,    g_f16);
    cudaGetSymbolAddress((void**)&attn16, g_attn16);
    cudaGetSymbolAddress((void**)&w16,    g_w16);
    cudaGetSymbolAddress((void**)&x1,     g_x1);

    cudaFuncSetAttribute(attn_fused_kernel, cudaFuncAttributeMaxDynamicSharedMemorySize, 57344);

    // 0. convert all weights to fp16 in one launch
    f2h_all_kernel<<<(int)(E3 / 256), 256>>>((const float4*)qkv_w, (const float4*)out_w,
                                             (const float4*)ffn_in_w, (const float4*)ffn_out_w,
                                             (__half2*)w16);
    // 1. h16 = LN1(x)
    ln_kernel<<<BL, 256>>>(x, ln1_w, ln1_b, h16);
    // 2. qkv16 = h16 @ qkv_w + qkv_b
    gemm16_kernel<0><<<dim3(D3 / 128, BL / 128), 256>>>(h16, w16 + OFF_QKVW, qkv_b, qkv16, nullptr, nullptr, nullptr, D3, Dd);
    // 3. fused attention: e16, p32 -> d_out, o16
    attn_fused_kernel<<<dim3(Ll / 128, Bb * Hh), 256, 56832>>>(qkv16, rel_bias, attn16, attn, o16);
    // 4. x1 = x + (o16 @ out_w + out_b) * gamma1
    gemm16_kernel<1><<<dim3(Dd / 128, BL / 128), 256>>>(o16, w16 + OFF_OUTW, out_b, nullptr, x1, x, gamma1, Dd, Dd);
    // 5. h16 = LN2(x1)
    ln_kernel<<<BL, 256>>>(x1, ln2_w, ln2_b, h16);
    // 6. f16 = geglu(h16 @ ffn_in_w + b)
    gemm_geglu_kernel<<<dim3(DH / 64, BL / 128), 256>>>(h16, w16 + OFF_FFNIN, ffn_in_b, f16);
    // 7. out_x = x1 + (f16 @ ffn_out_w + b) * gamma2
    gemm16_kernel<1><<<dim3(Dd / 128, BL / 128), 256>>>(f16, w16 + OFF_FFNOUT, ffn_out_b, nullptr, out_x, x1, gamma2, Dd, DH);
}

// round 8
// speedup vs baseline: 1.6245x; 1.0098x over previous
#include <cuda_runtime.h>
#include <cuda_fp16.h>
#include <math.h>
#include <stdint.h>

// Problem constants
constexpr int Bb  = 2;
constexpr int Ll  = 2048;
constexpr int Dd  = 512;
constexpr int Hh  = 8;
constexpr int HD  = 64;
constexpr int DH  = 2048;
constexpr int MREL = 128;
constexpr int D3  = 3 * Dd;    // 1536
constexpr int BL  = Bb * Ll;   // 4096
constexpr long long XSIZE  = (long long)BL * Dd;
constexpr long long ATTN_N = (long long)Bb * Hh * Ll * Ll;  // 67,108,864
constexpr int NROWS = Bb * Hh * Ll;   // 32768

// fp16 staging buffers
__device__ __half g_h16  [BL * Dd];
__device__ __half g_qkv16[BL * D3];
__device__ __half g_o16  [BL * Dd];
__device__ __half g_f16  [BL * DH];
__device__ __half g_attn16[ATTN_N];   // fp16 unnormalized exp(score)
// fp16 weights: qkv_w | out_w | ffn_in_w | ffn_out_w  (contiguous)
constexpr long long OFF_QKVW   = 0;
constexpr long long OFF_OUTW   = OFF_QKVW  + (long long)Dd * D3;
constexpr long long OFF_FFNIN  = OFF_OUTW  + (long long)Dd * Dd;
constexpr long long OFF_FFNOUT = OFF_FFNIN + (long long)Dd * 2 * DH;
constexpr long long W16_TOTAL  = OFF_FFNOUT + (long long)DH * Dd;   // 4,194,304
__device__ __half g_w16[W16_TOTAL];
__device__ float  g_x1  [BL * Dd];
__device__ float  g_inv [NROWS];      // 1/rowsum

// ---------------- helpers ----------------
static __device__ __forceinline__ uint32_t sm32(const void* p) {
    return (uint32_t)__cvta_generic_to_shared(p);
}
static __device__ __forceinline__ void cp16(void* dst, const void* src) {
    asm volatile("cp.async.cg.shared.global [%0], [%1], 16;\n"
                 :: "r"(sm32(dst)), "l"(__cvta_generic_to_global(src)));
}
static __device__ __forceinline__ void cp_commit() {
    asm volatile("cp.async.commit_group;\n");
}
template <int N> static __device__ __forceinline__ void cp_wait() {
    asm volatile("cp.async.wait_group %0;\n" :: "n"(N));
}
static __device__ __forceinline__ void ldsm_x4(uint32_t& r0, uint32_t& r1, uint32_t& r2, uint32_t& r3, uint32_t a) {
    asm volatile("ldmatrix.sync.aligned.m8n8.x4.shared.b16 {%0,%1,%2,%3}, [%4];\n"
                 : "=r"(r0), "=r"(r1), "=r"(r2), "=r"(r3) : "r"(a));
}
static __device__ __forceinline__ void ldsm_x4t(uint32_t& r0, uint32_t& r1, uint32_t& r2, uint32_t& r3, uint32_t a) {
    asm volatile("ldmatrix.sync.aligned.m8n8.x4.trans.shared.b16 {%0,%1,%2,%3}, [%4];\n"
                 : "=r"(r0), "=r"(r1), "=r"(r2), "=r"(r3) : "r"(a));
}
static __device__ __forceinline__ void ldsm_x2t(uint32_t& r0, uint32_t& r1, uint32_t a) {
    asm volatile("ldmatrix.sync.aligned.m8n8.x2.trans.shared.b16 {%0,%1}, [%2];\n"
                 : "=r"(r0), "=r"(r1) : "r"(a));
}
static __device__ __forceinline__ void mma16(float* c, const uint32_t* a, const uint32_t* b) {
    asm volatile("mma.sync.aligned.m16n8k16.row.col.f32.f16.f16.f32 "
                 "{%0,%1,%2,%3}, {%4,%5,%6,%7}, {%8,%9}, {%0,%1,%2,%3};\n"
                 : "+f"(c[0]), "+f"(c[1]), "+f"(c[2]), "+f"(c[3])
                 : "r"(a[0]), "r"(a[1]), "r"(a[2]), "r"(a[3]), "r"(b[0]), "r"(b[1]));
}
static __device__ __forceinline__ int clampq(int d) {
    return d < -(MREL - 1) ? -(MREL - 1) : (d > (MREL - 1) ? (MREL - 1) : d);
}

// ---------------- all weights fp32 -> fp16, one launch ----------------
constexpr long long E0 = OFF_OUTW   / 4;
constexpr long long E1 = OFF_FFNIN  / 4;
constexpr long long E2 = OFF_FFNOUT / 4;
constexpr long long E3 = W16_TOTAL  / 4;
__global__ void f2h_all_kernel(const float4* __restrict__ a, const float4* __restrict__ b,
                               const float4* __restrict__ c, const float4* __restrict__ d,
                               __half2* __restrict__ dst) {
    long long i = (long long)blockIdx.x * 256 + threadIdx.x;
    const float4* src; long long off;
    if (i < E0)      { src = a; off = 0;  }
    else if (i < E1) { src = b; off = E0; }
    else if (i < E2) { src = c; off = E1; }
    else             { src = d; off = E2; }
    float4 v = src[i - off];
    dst[i * 2]     = __floats2half2_rn(v.x, v.y);
    dst[i * 2 + 1] = __floats2half2_rn(v.z, v.w);
}

// ---------------- LayerNorm -> fp16 out ----------------
__global__ void ln_kernel(const float* __restrict__ x, const float* __restrict__ w,
                          const float* __restrict__ b, __half* __restrict__ out) {
    int row = blockIdx.x;
    const float* xr = x + (long long)row * Dd;
    int t = threadIdx.x; // 256
    float v0 = xr[t], v1 = xr[t + 256];
    __shared__ float red[256];
    red[t] = v0 + v1;
    __syncthreads();
    #pragma unroll
    for (int o = 128; o > 0; o >>= 1) { if (t < o) red[t] += red[t + o]; __syncthreads(); }
    float mu = red[0] * (1.0f / Dd);
    __syncthreads();
    float d0 = v0 - mu, d1 = v1 - mu;
    red[t] = d0 * d0 + d1 * d1;
    __syncthreads();
    #pragma unroll
    for (int o = 128; o > 0; o >>= 1) { if (t < o) red[t] += red[t + o]; __syncthreads(); }
    float rstd = rsqrtf(red[0] * (1.0f / Dd) + 1e-5f);
    __half* orow = out + (long long)row * Dd;
    orow[t]       = __float2half(d0 * rstd * w[t]       + b[t]);
    orow[t + 256] = __float2half(d1 * rstd * w[t + 256] + b[t + 256]);
}

// ---------------- Tensor-core GEMM, cp.async double-buffered ----------------
// MODE 0: half out = acc+bias.  MODE 1: float out = resid + (acc+bias)*gamma.
template <int MODE>
__global__ void gemm16_kernel(const __half* __restrict__ A, const __half* __restrict__ W,
                              const float* __restrict__ bias, __half* __restrict__ Ch,
                              float* __restrict__ Cf, const float* __restrict__ resid,
                              const float* __restrict__ gamma, int N, int K) {
    __shared__ __half As[2][128][40];
    __shared__ __half Bs[2][32][136];
    int bm = blockIdx.y * 128, bn = blockIdx.x * 128;
    int tid = threadIdx.x, lane = tid & 31, wid = tid >> 5;
    int wm0 = (wid & 1) * 64, wn0 = (wid >> 1) * 32;

    auto load = [&](int k0, int st) {
        #pragma unroll
        for (int i = 0; i < 2; i++) {
            int t = tid + i * 256;
            int r = t >> 2, s = t & 3;
            cp16(&As[st][r][s * 8], A + (size_t)(bm + r) * K + k0 + s * 8);
        }
        #pragma unroll
        for (int i = 0; i < 2; i++) {
            int t = tid + i * 256;
            int r = t >> 4, s = t & 15;
            cp16(&Bs[st][r][s * 8], W + (size_t)(k0 + r) * N + bn + s * 8);
        }
    };
    load(0, 0); cp_commit();
    float acc[4][4][4] = {};
    int nIter = K / 32;
    for (int it = 0; it < nIter; it++) {
        int cur = it & 1;
        if (it + 1 < nIter) { load((it + 1) * 32, cur ^ 1); cp_commit(); cp_wait<1>(); }
        else cp_wait<0>();
        __syncthreads();
        #pragma unroll
        for (int ks = 0; ks < 32; ks += 16) {
            uint32_t a[4][4], b[4][2];
            #pragma unroll
            for (int i = 0; i < 4; i++)
                ldsm_x4(a[i][0], a[i][1], a[i][2], a[i][3],
                        sm32(&As[cur][wm0 + i * 16 + (lane & 15)][ks + (lane >> 4) * 8]));
            #pragma unroll
            for (int j = 0; j < 4; j++)
                ldsm_x2t(b[j][0], b[j][1], sm32(&Bs[cur][ks + (lane & 15)][wn0 + j * 8]));
            #pragma unroll
            for (int i = 0; i < 4; i++)
                #pragma unroll
                for (int j = 0; j < 4; j++) mma16(acc[i][j], a[i], b[j]);
        }
        __syncthreads();
    }
    #pragma unroll
    for (int i = 0; i < 4; i++) {
        #pragma unroll
        for (int j = 0; j < 4; j++) {
            int r = bm + wm0 + i * 16 + (lane >> 2);
            int c = bn + wn0 + j * 8 + (lane & 3) * 2;
            #pragma unroll
            for (int hh = 0; hh < 2; hh++) {
                size_t idx = (size_t)(r + hh * 8) * N + c;
                float v0 = acc[i][j][hh * 2]     + bias[c];
                float v1 = acc[i][j][hh * 2 + 1] + bias[c + 1];
                if (MODE == 0) {
                    *(__half2*)(Ch + idx) = __floats2half2_rn(v0, v1);
                } else {
                    float2 rv = *(const float2*)(resid + idx);
                    float2 ov = make_float2(rv.x + v0 * gamma[c], rv.y + v1 * gamma[c + 1]);
                    *(float2*)(Cf + idx) = ov;
                }
            }
        }
    }
}

// ---------------- Attention pass 1: S->exp->e16 store + register P -> O=PV, rowsums ----------------
// Grid (16 q-tiles, 16 bh), 256 threads. Each warp owns 16 full q-rows.
// smem: Qs[128*72] | stage0{K[128*72] V[128*72]} | stage1{...}  = 92160 B
__global__ void __launch_bounds__(256, 2)
attn_pass1_kernel(const __half* __restrict__ qkv, const float* __restrict__ rel_bias,
                  __half* __restrict__ e16, float* __restrict__ invg,
                  __half* __restrict__ o16) {
    extern __shared__ __align__(16) char dsm[];
    __half* Qs = (__half*)dsm;
    __half* Kbuf[2] = { (__half*)(dsm + 18432), (__half*)(dsm + 55296) };
    __half* Vbuf[2] = { (__half*)(dsm + 36864), (__half*)(dsm + 73728) };
    __shared__ float rb_s[2 * MREL - 1];

    int bh = blockIdx.y, b = bh >> 3, h = bh & 7;
    int q0 = blockIdx.x * 128;
    int tid = threadIdx.x, lane = tid & 31, wid = tid >> 5;
    int wm0 = wid * 16;
    if (tid < 2 * MREL - 1) rb_s[tid] = rel_bias[h * (2 * MREL - 1) + tid];

    const __half* Qg = qkv + (size_t)b * Ll * D3 + h * HD;
    const __half* Kg = Qg + Dd;
    const __half* Vg = Qg + 2 * Dd;
    __half* Eg = e16 + ((size_t)bh * Ll + q0) * Ll;

    // load Q once
    #pragma unroll
    for (int i = 0; i < 4; i++) {
        int t = tid + i * 256;
        int r = t >> 3, s = t & 7;
        *(uint4*)(Qs + r * 72 + s * 8) = *(const uint4*)(Qg + (size_t)(q0 + r) * D3 + s * 8);
    }

    auto loadKV = [&](int kt, int st) {
        const __half* kb = Kg + (size_t)(kt * 128) * D3;
        const __half* vb = Vg + (size_t)(kt * 128) * D3;
        #pragma unroll
        for (int i = 0; i < 4; i++) {
            int t = tid + i * 256;
            int r = t >> 3, s = t & 7;
            cp16(Kbuf[st] + r * 72 + s * 8, kb + (size_t)r * D3 + s * 8);
            cp16(Vbuf[st] + r * 72 + s * 8, vb + (size_t)r * D3 + s * 8);
        }
    };
    loadKV(0, 0); cp_commit();

    const float scale = 0.125f;
    float acc_o[8][4] = {};
    float esum0 = 0.f, esum1 = 0.f;
    int rloc0 = wm0 + (lane >> 2);      // local q row (and +8)
    int qg0 = q0 + rloc0, qg1 = qg0 + 8;

    for (int kt = 0; kt < 16; kt++) {
        int cur = kt & 1;
        if (kt + 1 < 16) { loadKV(kt + 1, cur ^ 1); cp_commit(); cp_wait<1>(); }
        else cp_wait<0>();
        __syncthreads();
        __half* Kc = Kbuf[cur];
        __half* Vc = Vbuf[cur];

        // ---- S = Q K^T (16 q-rows x 128 k-cols per warp) ----
        float acc_s[16][4];
        #pragma unroll
        for (int j = 0; j < 16; j++)
            acc_s[j][0] = acc_s[j][1] = acc_s[j][2] = acc_s[j][3] = 0.f;
        #pragma unroll
        for (int ks = 0; ks < 4; ks++) {
            uint32_t qa[4];
            ldsm_x4(qa[0], qa[1], qa[2], qa[3],
                    sm32(Qs + (wm0 + (lane & 15)) * 72 + ks * 16 + (lane >> 4) * 8));
            #pragma unroll
            for (int jp = 0; jp < 8; jp++) {
                uint32_t kb[4];
                ldsm_x4(kb[0], kb[1], kb[2], kb[3],
                        sm32(Kc + ((jp * 2 + (lane >> 4)) * 8 + (lane & 7)) * 72
                             + ks * 16 + ((lane >> 3) & 1) * 8));
                mma16(acc_s[jp * 2],     qa, &kb[0]);
                mma16(acc_s[jp * 2 + 1], qa, &kb[2]);
            }
        }

        // ---- epilogue: e = exp(s*scale + rb), store e16, pack A-frags ----
        int k0 = kt * 128;
        int dt = q0 - k0;
        bool cst = (dt >= 254) || (dt <= -254);
        float rbc = (dt >= 254) ? rb_s[2 * MREL - 2] : rb_s[0];
        uint32_t af[8][4];
        #pragma unroll
        for (int jp = 0; jp < 8; jp++) {
            #pragma unroll
            for (int t = 0; t < 2; t++) {
                int j = jp * 2 + t;
                int kkg = k0 + j * 8 + (lane & 3) * 2;
                float rb00 = cst ? rbc : rb_s[clampq(qg0 - kkg)     + MREL - 1];
                float rb01 = cst ? rbc : rb_s[clampq(qg0 - kkg - 1) + MREL - 1];
                float rb10 = cst ? rbc : rb_s[clampq(qg1 - kkg)     + MREL - 1];
                float rb11 = cst ? rbc : rb_s[clampq(qg1 - kkg - 1) + MREL - 1];
                float e0 = __expf(acc_s[j][0] * scale + rb00);
                float e1 = __expf(acc_s[j][1] * scale + rb01);
                float e2 = __expf(acc_s[j][2] * scale + rb10);
                float e3 = __expf(acc_s[j][3] * scale + rb11);
                __half2 h01 = __floats2half2_rn(e0, e1);
                __half2 h23 = __floats2half2_rn(e2, e3);
                *(__half2*)(Eg + (size_t)rloc0 * Ll + kkg)       = h01;
                *(__half2*)(Eg + (size_t)(rloc0 + 8) * Ll + kkg) = h23;
                esum0 += e0 + e1;
                esum1 += e2 + e3;
                af[jp][t * 2]     = *(uint32_t*)&h01;
                af[jp][t * 2 + 1] = *(uint32_t*)&h23;
            }
        }

        // ---- O += P @ V (register A-frags) ----
        #pragma unroll
        for (int jp = 0; jp < 8; jp++) {
            #pragma unroll
            for (int np = 0; np < 4; np++) {
                uint32_t vb[4];
                ldsm_x4t(vb[0], vb[1], vb[2], vb[3],
                         sm32(Vc + (jp * 16 + (lane & 7) + ((lane >> 3) & 1) * 8) * 72
                              + (np * 2 + (lane >> 4)) * 8));
                mma16(acc_o[np * 2],     af[jp], &vb[0]);
                mma16(acc_o[np * 2 + 1], af[jp], &vb[2]);
            }
        }
        __syncthreads();
    }

    // ---- rowsums (quad reduce), inv, write inv + o16 ----
    esum0 += __shfl_xor_sync(0xffffffffu, esum0, 1);
    esum0 += __shfl_xor_sync(0xffffffffu, esum0, 2);
    esum1 += __shfl_xor_sync(0xffffffffu, esum1, 1);
    esum1 += __shfl_xor_sync(0xffffffffu, esum1, 2);
    float inv0 = 1.0f / esum0, inv1 = 1.0f / esum1;
    if ((lane & 3) == 0) {
        invg[(size_t)bh * Ll + qg0] = inv0;
        invg[(size_t)bh * Ll + qg1] = inv1;
    }
    #pragma unroll
    for (int n = 0; n < 8; n++) {
        int c = n * 8 + (lane & 3) * 2;
        __half* dst = o16 + (size_t)(b * Ll + qg0) * Dd + h * HD + c;
        *(__half2*)dst = __floats2half2_rn(acc_o[n][0] * inv0, acc_o[n][1] * inv0);
        *(__half2*)(dst + (size_t)8 * Dd) = __floats2half2_rn(acc_o[n][2] * inv1, acc_o[n][3] * inv1);
    }
}

// ---------------- Emit: p32[row,k] = e16[row,k] * inv[row] (pure stream) ----------------
__global__ void emit_kernel(const __half* __restrict__ e16, const float* __restrict__ invg,
                            float* __restrict__ attnf) {
    int row = blockIdx.x;
    int t = threadIdx.x;   // 256; one uint4 (8 halves) per thread
    float inv = invg[row];
    uint4 v = ((const uint4*)(e16 + (size_t)row * Ll))[t];
    float4* dst = (float4*)(attnf + (size_t)row * Ll);
    float2 f0 = __half22float2(*(__half2*)&v.x);
    float2 f1 = __half22float2(*(__half2*)&v.y);
    float2 f2 = __half22float2(*(__half2*)&v.z);
    float2 f3 = __half22float2(*(__half2*)&v.w);
    dst[t * 2]     = make_float4(f0.x * inv, f0.y * inv, f1.x * inv, f1.y * inv);
    dst[t * 2 + 1] = make_float4(f2.x * inv, f2.y * inv, f3.x * inv, f3.y * inv);
}

// ---------------- FFN-in GEMM + fused GEGLU, cp.async double-buffered ----------------
__global__ void gemm_geglu_kernel(const __half* __restrict__ A, const __half* __restrict__ W,
                                  const float* __restrict__ bias, __half* __restrict__ F) {
    __shared__ __half As[2][128][40];
    __shared__ __half Bs[2][2][32][72];
    int bm = blockIdx.y * 128, bn = blockIdx.x * 64;
    int tid = threadIdx.x, lane = tid & 31, wid = tid >> 5;
    int wm = (wid >> 1) * 32, wn = (wid & 1) * 32;
    float acc[2][2][4][4] = {};
    auto load = [&](int k0, int st) {
        #pragma unroll
        for (int i = 0; i < 2; i++) {
            int t = tid + i * 256;
            int r = t >> 2, s = t & 3;
            cp16(&As[st][r][s * 8], A + (size_t)(bm + r) * Dd + k0 + s * 8);
        }
        {
            int r = tid >> 3, s = tid & 7;
            #pragma unroll
            for (int hh = 0; hh < 2; hh++)
                cp16(&Bs[st][hh][r][s * 8],
                     W + (size_t)(k0 + r) * (2 * DH) + bn + hh * DH + s * 8);
        }
    };
    load(0, 0); cp_commit();
    constexpr int NIT = Dd / 32;
    for (int it = 0; it < NIT; it++) {
        int cur = it & 1;
        if (it + 1 < NIT) { load((it + 1) * 32, cur ^ 1); cp_commit(); cp_wait<1>(); }
        else cp_wait<0>();
        __syncthreads();
        #pragma unroll
        for (int ks = 0; ks < 32; ks += 16) {
            uint32_t a[2][4];
            #pragma unroll
            for (int mi = 0; mi < 2; mi++)
                ldsm_x4(a[mi][0], a[mi][1], a[mi][2], a[mi][3],
                        sm32(&As[cur][wm + mi * 16 + (lane & 15)][ks + (lane >> 4) * 8]));
            #pragma unroll
            for (int hh = 0; hh < 2; hh++)
                #pragma unroll
                for (int nj = 0; nj < 4; nj++) {
                    uint32_t bfr[2];
                    ldsm_x2t(bfr[0], bfr[1], sm32(&Bs[cur][hh][ks + (lane & 15)][wn + nj * 8]));
                    #pragma unroll
                    for (int mi = 0; mi < 2; mi++) mma16(acc[hh][mi][nj], a[mi], bfr);
                }
        }
        __syncthreads();
    }
    #pragma unroll
    for (int mi = 0; mi < 2; mi++) {
        #pragma unroll
        for (int nj = 0; nj < 4; nj++) {
            int r = bm + wm + mi * 16 + (lane >> 2);
            int c = bn + wn + nj * 8 + (lane & 3) * 2;
            float ba0 = bias[c], ba1 = bias[c + 1];
            float bb0 = bias[c + DH], bb1 = bias[c + DH + 1];
            #pragma unroll
            for (int hh = 0; hh < 2; hh++) {
                float av0 = acc[0][mi][nj][hh * 2]     + ba0;
                float av1 = acc[0][mi][nj][hh * 2 + 1] + ba1;
                float bg0 = acc[1][mi][nj][hh * 2]     + bb0;
                float bg1 = acc[1][mi][nj][hh * 2 + 1] + bb1;
                float g0 = 0.5f * bg0 * (1.0f + erff(bg0 * 0.70710678118654752f));
                float g1 = 0.5f * bg1 * (1.0f + erff(bg1 * 0.70710678118654752f));
                size_t idx = (size_t)(r + hh * 8) * DH + c;
                *(__half2*)(F + idx) = __floats2half2_rn(g0 * av0, g1 * av1);
            }
        }
    }
}

extern "C" void kernel_launch(void* const* d_in, const int* in_sizes, int n_in,
                              void* d_out, int out_size) {
    const float* x        = (const float*)d_in[0];
    const float* ln1_w    = (const float*)d_in[1];
    const float* ln1_b    = (const float*)d_in[2];
    const float* qkv_w    = (const float*)d_in[3];
    const float* qkv_b    = (const float*)d_in[4];
    const float* out_w    = (const float*)d_in[5];
    const float* out_b    = (const float*)d_in[6];
    const float* rel_bias = (const float*)d_in[7];
    const float* gamma1   = (const float*)d_in[8];
    const float* ln2_w    = (const float*)d_in[9];
    const float* ln2_b    = (const float*)d_in[10];
    const float* ffn_in_w = (const float*)d_in[11];
    const float* ffn_in_b = (const float*)d_in[12];
    const float* ffn_out_w= (const float*)d_in[13];
    const float* ffn_out_b= (const float*)d_in[14];
    const float* gamma2   = (const float*)d_in[15];

    float* out_x = (float*)d_out;
    float* attn  = (float*)d_out + XSIZE;

    __half *h16, *qkv16, *o16, *f16, *attn16, *w16;
    float *x1, *invs;
    cudaGetSymbolAddress((void**)&h16,    g_h16);
    cudaGetSymbolAddress((void**)&qkv16,  g_qkv16);
    cudaGetSymbolAddress((void**)&o16,    g_o16);
    cudaGetSymbolAddress((void**)&f16,    g_f16);
    cudaGetSymbolAddress((void**)&attn16, g_attn16);
    cudaGetSymbolAddress((void**)&w16,    g_w16);
    cudaGetSymbolAddress((void**)&x1,     g_x1);
    cudaGetSymbolAddress((void**)&invs,   g_inv);

    cudaFuncSetAttribute(attn_pass1_kernel, cudaFuncAttributeMaxDynamicSharedMemorySize, 92160);

    // 0. convert all weights to fp16 in one launch
    f2h_all_kernel<<<(int)(E3 / 256), 256>>>((const float4*)qkv_w, (const float4*)out_w,
                                             (const float4*)ffn_in_w, (const float4*)ffn_out_w,
                                             (__half2*)w16);
    // 1. h16 = LN1(x)
    ln_kernel<<<BL, 256>>>(x, ln1_w, ln1_b, h16);
    // 2. qkv16 = h16 @ qkv_w + qkv_b
    gemm16_kernel<0><<<dim3(D3 / 128, BL / 128), 256>>>(h16, w16 + OFF_QKVW, qkv_b, qkv16, nullptr, nullptr, nullptr, D3, Dd);
    // 3. attention pass1: e16, inv, o16 (flash-style, register P)
    attn_pass1_kernel<<<dim3(Ll / 128, Bb * Hh), 256, 92160>>>(qkv16, rel_bias, attn16, invs, o16);
    // 4. emit fp32 probs -> d_out (pure stream)
    emit_kernel<<<NROWS, 256>>>(attn16, invs, attn);
    // 5. x1 = x + (o16 @ out_w + out_b) * gamma1
    gemm16_kernel<1><<<dim3(Dd / 128, BL / 128), 256>>>(o16, w16 + OFF_OUTW, out_b, nullptr, x1, x, gamma1, Dd, Dd);
    // 6. h16 = LN2(x1)
    ln_kernel<<<BL, 256>>>(x1, ln2_w, ln2_b, h16);
    // 7. f16 = geglu(h16 @ ffn_in_w + b)
    gemm_geglu_kernel<<<dim3(DH / 64, BL / 128), 256>>>(h16, w16 + OFF_FFNIN, ffn_in_b, f16);
    // 8. out_x = x1 + (f16 @ ffn_out_w + b) * gamma2
    gemm16_kernel<1><<<dim3(Dd / 128, BL / 128), 256>>>(f16, w16 + OFF_FFNOUT, ffn_out_b, nullptr, out_x, x1, gamma2, Dd, DH);
}